// round 5
// baseline (speedup 1.0000x reference)
#include <cuda_runtime.h>
#include <math.h>

#define NN 16384
#define EE 262144
typedef unsigned long long ull;

__device__ float g_ns  [NN * 120];
__device__ float g_ne  [NN * 240];
__device__ float g_qinv[NN * 120];
__device__ float g_kinv[NN * 120];
__device__ float g_vinv[NN * 120];
__device__ float g_qsph[NN * 120];
__device__ float g_ksph[NN * 120];
__device__ float g_vsph[NN * 112];
__device__ float g_h   [(size_t)EE * 240];
__device__ float g_w   [(size_t)EE * 120];

__device__ __forceinline__ ull pack2(float x, float y){ ull r; asm("mov.b64 %0,{%1,%2};":"=l"(r):"f"(x),"f"(y)); return r; }
__device__ __forceinline__ void unpack2(ull v, float&x, float&y){ asm("mov.b64 {%0,%1},%2;":"=f"(x),"=f"(y):"l"(v)); }
__device__ __forceinline__ void fma2(ull&d, ull a, ull b){ asm("fma.rn.f32x2 %0,%1,%2,%0;":"+l"(d):"l"(a),"l"(b)); }
__device__ __forceinline__ float4 ldg4(const float* p){ return __ldg(reinterpret_cast<const float4*>(p)); }
__device__ __forceinline__ void red4(float* p, float a, float b, float c, float d){
    asm volatile("red.global.add.v4.f32 [%0],{%1,%2,%3,%4};"::"l"(p),"f"(a),"f"(b),"f"(c),"f"(d):"memory");
}
__device__ __forceinline__ float wsum(float v){
    #pragma unroll
    for (int o=16;o;o>>=1) v += __shfl_xor_sync(0xffffffffu, v, o);
    return v;
}
__device__ __forceinline__ unsigned smem_u32(const void* p){
    unsigned a; asm("{ .reg .u64 t; cvta.to.shared.u64 t, %1; cvt.u32.u64 %0, t; }":"=r"(a):"l"(p)); return a;
}
__device__ __forceinline__ void cpasync16(unsigned dst, const float* src){
    asm volatile("cp.async.ca.shared.global [%0], [%1], 16;"::"r"(dst),"l"(src));
}
__device__ __forceinline__ void cpcommit(){ asm volatile("cp.async.commit_group;"::); }
__device__ __forceinline__ void sts_zero16(unsigned dst){
    asm volatile("st.shared.v4.b32 [%0], {%1,%1,%1,%1};"::"r"(dst),"r"(0):"memory");
}

// acc += Ash[k][4rt..4rt+3] * Bsh[k][colBase..colBase+15]
__device__ __forceinline__ void gemm_chunk(const float* __restrict__ Ash, const float* __restrict__ Bsh,
                                           int klen, int rt, int colBase, ull acc[4][8]){
    #pragma unroll 4
    for (int k=0;k<klen;k++){
        float4 a4 = *reinterpret_cast<const float4*>(Ash + k*132 + (rt<<2));
        ull ap0=pack2(a4.x,a4.x), ap1=pack2(a4.y,a4.y), ap2=pack2(a4.z,a4.z), ap3=pack2(a4.w,a4.w);
        const ulonglong2* bp = reinterpret_cast<const ulonglong2*>(Bsh + k*128 + colBase);
        ulonglong2 b01=bp[0], b23=bp[1], b45=bp[2], b67=bp[3];
        ull bb[8] = {b01.x,b01.y,b23.x,b23.y,b45.x,b45.y,b67.x,b67.y};
        #pragma unroll
        for (int j=0;j<8;j++){
            fma2(acc[0][j],ap0,bb[j]); fma2(acc[1][j],ap1,bb[j]);
            fma2(acc[2][j],ap2,bb[j]); fma2(acc[3][j],ap3,bb[j]);
        }
    }
}

// staged transpose epilogue -> coalesced float4 stores of 120 cols
__device__ __forceinline__ void epilogue_store(
    ull acc[4][8], const float* __restrict__ sb, const float* __restrict__ fc,
    int fuseSilu, float* __restrict__ out, int ldout, int colOff, int e0,
    float* stage, int rt, int colBase, int tid)
{
    #pragma unroll
    for (int g=0; g<4; g++){
        __syncthreads();
        if ((rt>>3) == g){
            #pragma unroll
            for (int r=0;r<4;r++){
                int lrow = 4*(rt - 8*g) + r;
                int grow = 4*rt + r;
                float f = fc ? fc[grow] : 1.f;
                #pragma unroll
                for (int j=0;j<8;j++){
                    float lo,hi; unpack2(acc[r][j],lo,hi);
                    int c0 = colBase + 2*j;
                    float x0 = lo + sb[c0], x1 = hi + sb[c0+1];
                    if (fuseSilu){ x0 = x0/(1.f+__expf(-x0)); x1 = x1/(1.f+__expf(-x1)); }
                    stage[lrow*128 + c0]   = x0*f;
                    stage[lrow*128 + c0+1] = x1*f;
                }
            }
        }
        __syncthreads();
        for (int idx=tid; idx<960; idx+=256){
            int row = idx/30, q = idx - row*30;
            float4 v = *reinterpret_cast<float4*>(stage + row*128 + 4*q);
            *reinterpret_cast<float4*>(out + (size_t)(e0+32*g+row)*ldout + colOff + 4*q) = v;
        }
    }
    __syncthreads();
}

// ---------- K0: residual init ----------
__global__ void init_out_kernel(const float* __restrict__ xs, const float* __restrict__ xe, float* __restrict__ out){
    size_t i = (size_t)blockIdx.x*blockDim.x + threadIdx.x;
    size_t ns = (size_t)NN*120, ne = (size_t)NN*240;
    if (i < ns) out[i] = xs[i];
    if (i < ne) out[ns + i] = xe[i];
}

// ---------- K1: node LayerNorm + O3 LayerNorm ----------
__global__ void node_norm_kernel(const float* __restrict__ xs_in, const float* __restrict__ xe_in,
                                 const float* __restrict__ lnw, const float* __restrict__ lnb,
                                 const float* __restrict__ o3w){
    int lane = threadIdx.x & 31;
    int node = blockIdx.x*4 + (threadIdx.x >> 5);
    if (node >= NN) return;
    const float* xs = xs_in + (size_t)node*120;
    float v0=xs[lane], v1=xs[lane+32], v2=xs[lane+64], v3=(lane<24)?xs[lane+96]:0.f;
    float s = wsum(v0+v1+v2+v3);
    float q = wsum(v0*v0+v1*v1+v2*v2+v3*v3);
    float mean = s*(1.f/120.f);
    float inv = rsqrtf(q*(1.f/120.f) - mean*mean + 1e-5f);
    float* ns = g_ns + (size_t)node*120;
    ns[lane]    = (v0-mean)*inv*__ldg(lnw+lane)    + __ldg(lnb+lane);
    ns[lane+32] = (v1-mean)*inv*__ldg(lnw+lane+32) + __ldg(lnb+lane+32);
    ns[lane+64] = (v2-mean)*inv*__ldg(lnw+lane+64) + __ldg(lnb+lane+64);
    if (lane<24) ns[lane+96] = (v3-mean)*inv*__ldg(lnw+lane+96) + __ldg(lnb+lane+96);

    const float* xe = xe_in + (size_t)node*240;
    float* ne = g_ne + (size_t)node*240;
    {
        float e0=xe[lane], e1=xe[lane+32];
        float m = wsum(e0+e1)*(1.f/64.f);
        float c0=e0-m, c1=e1-m;
        float r = rsqrtf(wsum(c0*c0+c1*c1)*(1.f/64.f) + 1e-5f);
        ne[lane]    = c0*r*__ldg(o3w+lane);
        ne[lane+32] = c1*r*__ldg(o3w+lane+32);
    }
    {
        float y0=xe[64+lane], y1=xe[96+lane], y2=xe[128+lane];
        float r = rsqrtf(wsum(y0*y0+y1*y1+y2*y2)*(1.f/96.f) + 1e-5f);
        ne[64+lane]  = y0*r*__ldg(o3w+64+(lane)/3);
        ne[96+lane]  = y1*r*__ldg(o3w+64+(32+lane)/3);
        ne[128+lane] = y2*r*__ldg(o3w+64+(64+lane)/3);
    }
    {
        float z0=xe[160+lane], z1=xe[192+lane], z2=(lane<16)?xe[224+lane]:0.f;
        float r = rsqrtf(wsum(z0*z0+z1*z1+z2*z2)*(1.f/80.f) + 1e-5f);
        ne[160+lane] = z0*r*__ldg(o3w+96+(lane)/5);
        ne[192+lane] = z1*r*__ldg(o3w+96+(32+lane)/5);
        if (lane<16) ne[224+lane] = z2*r*__ldg(o3w+96+(64+lane)/5);
    }
}

// ---------- K2: 6 projections in one launch ----------
__global__ __launch_bounds__(256) void proj_kernel(
    const float* __restrict__ W0, const float* __restrict__ W1, const float* __restrict__ W2,
    const float* __restrict__ W3, const float* __restrict__ W4, const float* __restrict__ W5)
{
    __shared__ alignas(16) float Bsh[32*128];
    __shared__ alignas(16) float Ash[32*132];
    int sel = blockIdx.y;
    const float* B = (sel==0)?W0:(sel==1)?W1:(sel==2)?W2:(sel==3)?W3:(sel==4)?W4:W5;
    float* C = (sel==0)?g_qinv:(sel==1)?g_kinv:(sel==2)?g_vinv:(sel==3)?g_qsph:(sel==4)?g_ksph:g_vsph;
    int ncols = (sel==5)?112:120;
    const float* A = g_ns;

    int tid = threadIdx.x;
    int ct = tid>>5, rt = tid&31;
    int rowBase = blockIdx.x*128, colBase = ct*16;
    ull acc[4][8];
    #pragma unroll
    for (int r=0;r<4;r++){
        #pragma unroll
        for (int j=0;j<8;j++) acc[r][j]=0ull;
    }
    for (int kc=0; kc<120; kc+=32){
        int klen = min(32, 120-kc);
        __syncthreads();
        for (int idx=tid; idx<klen*128; idx+=256){
            int k = idx>>7, j = idx&127;
            Bsh[idx] = (j<ncols) ? __ldg(B + (kc+k)*ncols + j) : 0.f;
        }
        for (int idx=tid; idx<128*klen; idx+=256){
            int row=idx/klen, kk=idx-row*klen;
            Ash[kk*132+row] = A[(size_t)(rowBase+row)*120 + kc+kk];
        }
        __syncthreads();
        gemm_chunk(Ash, Bsh, klen, rt, colBase, acc);
    }
    #pragma unroll
    for (int r=0;r<4;r++){
        int row = rowBase + rt*4 + r;
        #pragma unroll
        for (int j=0;j<8;j++){
            float lo,hi; unpack2(acc[r][j],lo,hi);
            int c0 = colBase + 2*j;
            if (c0   < ncols) C[(size_t)row*ncols + c0]   = lo;
            if (c0+1 < ncols) C[(size_t)row*ncols + c0+1] = hi;
        }
    }
}

// ---------- kernel A: gather + equi_dot + both silu GEMMs -> g_h ----------
// smem floats: dsh[112*132] | bsh0[32*128] | bsh1[32*128] | sb1[128] | sb2[128]
#define A_DS 0
#define A_B0 14784
#define A_B1 18880
#define A_SB1 22976
#define A_SB2 23104
#define A_FLOATS 23232

__global__ __launch_bounds__(256) void edge_h_kernel(
    const int* __restrict__ ei, const float* __restrict__ rbf,
    const float* __restrict__ inv_w1, const float* __restrict__ inv_b1,
    const float* __restrict__ rbf_w1, const float* __restrict__ rbf_b1)
{
    extern __shared__ float sm[];
    float* dsh = sm + A_DS;
    float* bsh[2] = { sm + A_B0, sm + A_B1 };
    float* sb1 = sm + A_SB1;
    float* sb2 = sm + A_SB2;
    unsigned bsh_u32[2] = { smem_u32(bsh[0]), smem_u32(bsh[1]) };

    int tid = threadIdx.x;
    int warp = tid>>5, lane = tid&31;
    int rt = lane, colBase = warp*16;
    int e0 = blockIdx.x * 128;

    // phase 1: gather + equi_dot
    for (int el = warp; el < 128; el += 8){
        int e = e0 + el;
        int a_n = __ldg(ei+EE+e), b_n = __ldg(ei+e);
        const float* a = g_ne + (size_t)a_n*240;
        const float* b = g_ne + (size_t)b_n*240;
        { float d = __ldg(a+lane)-__ldg(b+lane);       dsh[lane*132+el] = d*d; }
        { float d = __ldg(a+lane+32)-__ldg(b+lane+32); dsh[(lane+32)*132+el] = d*d; }
        { int base = 64 + lane*3; float s=0.f;
          #pragma unroll
          for (int j=0;j<3;j++){ float d=__ldg(a+base+j)-__ldg(b+base+j); s+=d*d; }
          dsh[(64+lane)*132+el] = s; }
        if (lane<16){ int base = 160 + lane*5; float s=0.f;
          #pragma unroll
          for (int j=0;j<5;j++){ float d=__ldg(a+base+j)-__ldg(b+base+j); s+=d*d; }
          dsh[(96+lane)*132+el] = s; }
    }
    // rbf tile + rbf_w1 staged in bsh
    float* rbf_sh  = bsh[0];
    float* rbfW_sh = bsh[1];
    for (int idx=tid; idx<128*20; idx+=256){
        int el = idx/20, k = idx - el*20;
        rbf_sh[k*132+el] = __ldg(rbf + (size_t)e0*20 + idx);
    }
    for (int idx=tid; idx<20*128; idx+=256){
        int k = idx>>7, j = idx&127;
        rbfW_sh[idx] = (j<120) ? __ldg(rbf_w1 + k*120 + j) : 0.f;
    }
    if (tid < 128){
        sb1[tid] = (tid<120) ? __ldg(rbf_b1+tid) : 0.f;
        sb2[tid] = (tid<120) ? __ldg(inv_b1+tid) : 0.f;
    }
    __syncthreads();

    ull acc[4][8];

    // phase 2: h[:,120:240] = silu(rbf @ rbf_w1 + b1)
    #pragma unroll
    for (int r=0;r<4;r++){
        #pragma unroll
        for (int j=0;j<8;j++) acc[r][j]=0ull;
    }
    gemm_chunk(rbf_sh, rbfW_sh, 20, rt, colBase, acc);
    __syncthreads();
    // preload inv_w1 chunk0 into bsh0 while epilogue runs in bsh1
    for (int idx=tid; idx<32*32; idx+=256){
        int kk = idx>>5, j4 = idx&31;
        unsigned dst = bsh_u32[0] + (unsigned)(kk*128 + j4*4)*4u;
        if (j4 < 30) cpasync16(dst, inv_w1 + (size_t)kk*120 + j4*4);
        else sts_zero16(dst);
    }
    cpcommit();
    epilogue_store(acc, sb1, nullptr, 1, g_h, 240, 120, e0, bsh[1], rt, colBase, tid);

    // phase 3: h[:,0:120] = silu(d @ inv_w1 + b), K=112
    #pragma unroll
    for (int r=0;r<4;r++){
        #pragma unroll
        for (int j=0;j<8;j++) acc[r][j]=0ull;
    }
    const int NCH = 4;
    for (int c=0; c<NCH; c++){
        int kc = c*32;
        int klen = min(32, 112-kc);
        if (c+1 < NCH){
            int kc2 = (c+1)*32;
            int klen2 = min(32, 112-kc2);
            for (int idx=tid; idx<klen2*32; idx+=256){
                int kk = idx>>5, j4 = idx&31;
                unsigned dst = bsh_u32[(c+1)&1] + (unsigned)(kk*128 + j4*4)*4u;
                if (j4 < 30) cpasync16(dst, inv_w1 + (size_t)(kc2+kk)*120 + j4*4);
                else sts_zero16(dst);
            }
            cpcommit();
            asm volatile("cp.async.wait_group 1;"::);
        } else {
            asm volatile("cp.async.wait_group 0;"::);
        }
        __syncthreads();
        gemm_chunk(dsh + kc*132, bsh[c&1], klen, rt, colBase, acc);
        __syncthreads();
    }
    epilogue_store(acc, sb2, nullptr, 1, g_h, 240, 0, e0, bsh[0], rt, colBase, tid);
}

// ---------- kernel B: w = (h @ [inv_w2; rbf_w2] + b) * fcut ----------
// smem floats: Ash[32*132] | bsh0[32*128] | bsh1[32*128] | sb[128] | fc[128]
#define B_AS 0
#define B_B0 4224
#define B_B1 8320
#define B_SB 12416
#define B_FC 12544
#define B_FLOATS 12672

__global__ __launch_bounds__(256) void w_kernel(
    const float* __restrict__ fcut,
    const float* __restrict__ inv_w2, const float* __restrict__ inv_b2,
    const float* __restrict__ rbf_w2, const float* __restrict__ rbf_b2)
{
    extern __shared__ float sm[];
    float* Ash = sm + B_AS;
    float* bsh[2] = { sm + B_B0, sm + B_B1 };
    float* sb = sm + B_SB;
    float* fc = sm + B_FC;
    unsigned bsh_u32[2] = { smem_u32(bsh[0]), smem_u32(bsh[1]) };

    int tid = threadIdx.x;
    int rt = tid&31, colBase = (tid>>5)*16;
    int e0 = blockIdx.x * 128;

    if (tid < 128){
        sb[tid] = (tid<120) ? (__ldg(inv_b2+tid)+__ldg(rbf_b2+tid)) : 0.f;
        fc[tid] = __ldg(fcut + e0 + tid);
    }
    // preload chunk0
    for (int idx=tid; idx<32*32; idx+=256){
        int kk = idx>>5, j4 = idx&31;
        unsigned dst = bsh_u32[0] + (unsigned)(kk*128 + j4*4)*4u;
        if (j4 < 30) cpasync16(dst, inv_w2 + (size_t)kk*120 + j4*4);
        else sts_zero16(dst);
    }
    cpcommit();

    ull acc[4][8];
    #pragma unroll
    for (int r=0;r<4;r++){
        #pragma unroll
        for (int j=0;j<8;j++) acc[r][j]=0ull;
    }
    const int NCH = 8;
    for (int c=0; c<NCH; c++){
        int kc = c*32;
        int klen = min(32, 240-kc);
        // stage A tile (coalesced: one warp = one row x 32 cols)
        if (klen==32){
            for (int idx=tid; idx<128*32; idx+=256){
                int row = idx>>5, kk = idx&31;
                Ash[kk*132+row] = g_h[(size_t)(e0+row)*240 + kc+kk];
            }
        } else {
            for (int idx=tid; idx<128*klen; idx+=256){
                int row = idx/klen, kk = idx - row*klen;
                Ash[kk*132+row] = g_h[(size_t)(e0+row)*240 + kc+kk];
            }
        }
        if (c+1 < NCH){
            int kc2 = (c+1)*32;
            int klen2 = min(32, 240-kc2);
            for (int idx=tid; idx<klen2*32; idx+=256){
                int kk = idx>>5, j4 = idx&31;
                unsigned dst = bsh_u32[(c+1)&1] + (unsigned)(kk*128 + j4*4)*4u;
                if (j4 < 30){
                    int gk = kc2+kk;
                    const float* src = (gk<120) ? (inv_w2 + (size_t)gk*120 + j4*4)
                                                : (rbf_w2 + (size_t)(gk-120)*120 + j4*4);
                    cpasync16(dst, src);
                } else sts_zero16(dst);
            }
            cpcommit();
            asm volatile("cp.async.wait_group 1;"::);
        } else {
            asm volatile("cp.async.wait_group 0;"::);
        }
        __syncthreads();
        gemm_chunk(Ash, bsh[c&1], klen, rt, colBase, acc);
        __syncthreads();
    }
    epilogue_store(acc, sb, fc, 0, g_w, 120, 0, e0, bsh[0], rt, colBase, tid);
}

// ---------- K6: attention + gated messages + scatter ----------
__global__ __launch_bounds__(256) void edge_attn_kernel(const int* __restrict__ ei,
                                                        const float* __restrict__ fcut,
                                                        const float* __restrict__ rsh,
                                                        float* __restrict__ outS,
                                                        float* __restrict__ outE){
    __shared__ float sgate[8][116];
    int warp = threadIdx.x>>5, lane = threadIdx.x&31;
    int e = blockIdx.x*8 + warp;
    int ct = __ldg(ei+e), nb = __ldg(ei+EE+e);
    float fc = __ldg(fcut+e);
    const float* w  = g_w   + (size_t)e*120;
    const float* qi = g_qinv + (size_t)ct*120;
    const float* ki = g_kinv + (size_t)nb*120;
    const float* vi = g_vinv + (size_t)nb*120;
    const float* qs = g_qsph + (size_t)ct*120;
    const float* ks = g_ksph + (size_t)nb*120;
    const float* vs = g_vsph + (size_t)nb*112;

    float s0=0,s1=0,s2=0,s3=0,t0=0,t1=0,t2=0;
    if (lane < 30){
        float4 wv = ldg4(w + 4*lane);
        float4 q  = ldg4(qi + 4*lane), k = ldg4(ki + 4*lane);
        float4 qe = ldg4(qs + 4*lane), ke = ldg4(ks + 4*lane);
        float wa[4]={wv.x,wv.y,wv.z,wv.w};
        float pa[4]={q.x*k.x, q.y*k.y, q.z*k.z, q.w*k.w};
        float pe[4]={qe.x*ke.x, qe.y*ke.y, qe.z*ke.z, qe.w*ke.w};
        #pragma unroll
        for (int j=0;j<4;j++){
            int idx = 4*lane + j;
            float p = wa[j]*pa[j];
            float pq = wa[j]*pe[j];
            int h = idx/30, l = idx/40;
            s0 += (h==0)?p:0.f; s1 += (h==1)?p:0.f; s2 += (h==2)?p:0.f; s3 += (h==3)?p:0.f;
            t0 += (l==0)?pq:0.f; t1 += (l==1)?pq:0.f; t2 += (l==2)?pq:0.f;
        }
    }
    const float SC_S = 0.091287092917527686f;   // 1/sqrt(120)
    const float SC_E = 0.094491118252306805f;   // 1/sqrt(112)
    s0 = wsum(s0)*SC_S; s1 = wsum(s1)*SC_S; s2 = wsum(s2)*SC_S; s3 = wsum(s3)*SC_S;
    t0 = wsum(t0)*SC_E; t1 = wsum(t1)*SC_E; t2 = wsum(t2)*SC_E;

    if (lane < 30){
        float4 v = ldg4(vi + 4*lane);
        float va[4]={v.x,v.y,v.z,v.w}, m[4];
        #pragma unroll
        for (int j=0;j<4;j++){
            int h = (4*lane+j)/30;
            float ss = (h==0)?s0:((h==1)?s1:((h==2)?s2:s3));
            m[j] = ss*va[j];
        }
        red4(outS + (size_t)ct*120 + 4*lane, m[0],m[1],m[2],m[3]);
    }
    if (lane < 28){
        float4 v = ldg4(vs + 4*lane);
        float va[4]={v.x,v.y,v.z,v.w};
        #pragma unroll
        for (int j=0;j<4;j++){
            int ir = 4*lane + j;
            float tl = (ir<64)?t0:((ir<96)?t1:t2);
            sgate[warp][ir] = tl*va[j]*fc;
        }
    }
    __syncwarp();
    if (lane < 30){
        int base = 8*lane;
        float4 r0 = ldg4(rsh + (size_t)e*240 + base);
        float4 r1 = ldg4(rsh + (size_t)e*240 + base + 4);
        float ra[8]={r0.x,r0.y,r0.z,r0.w,r1.x,r1.y,r1.z,r1.w}, m[8];
        #pragma unroll
        for (int j=0;j<8;j++){
            int c = base + j;
            int ir = (c<64)? c : (c<160)? 64+(c-64)/3 : 96+(c-160)/5;
            m[j] = ra[j]*sgate[warp][ir];
        }
        red4(outE + (size_t)ct*240 + base,     m[0],m[1],m[2],m[3]);
        red4(outE + (size_t)ct*240 + base + 4, m[4],m[5],m[6],m[7]);
    }
}

extern "C" void kernel_launch(void* const* d_in, const int* in_sizes, int n_in,
                              void* d_out, int out_size){
    const float* node_scalar=(const float*)d_in[0];
    const float* node_equi  =(const float*)d_in[1];
    const float* rbf        =(const float*)d_in[2];
    const float* fcut       =(const float*)d_in[3];
    const float* rsh        =(const float*)d_in[4];
    const float* ln_w =(const float*)d_in[5];
    const float* ln_b =(const float*)d_in[6];
    const float* o3w  =(const float*)d_in[7];
    const float* Wq   =(const float*)d_in[8];
    const float* Wk   =(const float*)d_in[9];
    const float* Wv   =(const float*)d_in[10];
    const float* Wqs  =(const float*)d_in[11];
    const float* Wks  =(const float*)d_in[12];
    const float* Wvs  =(const float*)d_in[13];
    const float* rbf_w1=(const float*)d_in[14];
    const float* rbf_b1=(const float*)d_in[15];
    const float* rbf_w2=(const float*)d_in[16];
    const float* rbf_b2=(const float*)d_in[17];
    const float* inv_w1=(const float*)d_in[18];
    const float* inv_b1=(const float*)d_in[19];
    const float* inv_w2=(const float*)d_in[20];
    const float* inv_b2=(const float*)d_in[21];
    const int*   ei    =(const int*)d_in[22];

    float* outS = (float*)d_out;
    float* outE = outS + (size_t)NN*120;

    cudaFuncSetAttribute(edge_h_kernel, cudaFuncAttributeMaxDynamicSharedMemorySize, A_FLOATS*4);
    cudaFuncSetAttribute(w_kernel,      cudaFuncAttributeMaxDynamicSharedMemorySize, B_FLOATS*4);

    init_out_kernel<<<(NN*240 + 255)/256, 256>>>(node_scalar, node_equi, (float*)d_out);
    node_norm_kernel<<<NN/4, 128>>>(node_scalar, node_equi, ln_w, ln_b, o3w);
    proj_kernel<<<dim3(NN/128, 6), 256>>>(Wq, Wk, Wv, Wqs, Wks, Wvs);
    edge_h_kernel<<<EE/128, 256, A_FLOATS*4>>>(ei, rbf, inv_w1, inv_b1, rbf_w1, rbf_b1);
    w_kernel<<<EE/128, 256, B_FLOATS*4>>>(fcut, inv_w2, inv_b2, rbf_w2, rbf_b2);
    edge_attn_kernel<<<EE/8, 256>>>(ei, fcut, rsh, outS, outE);
}

// round 7
// speedup vs baseline: 1.4422x; 1.4422x over previous
#include <cuda_runtime.h>
#include <math.h>

#define NN 16384
#define EE 262144
typedef unsigned long long ull;
typedef unsigned int u32;

__device__ float g_ns  [NN * 120];
__device__ float g_ne  [NN * 240];
__device__ float g_qinv[NN * 120];
__device__ float g_kinv[NN * 120];
__device__ float g_vinv[NN * 120];
__device__ float g_qsph[NN * 120];
__device__ float g_ksph[NN * 120];
__device__ float g_vsph[NN * 112];
__device__ float g_w   [(size_t)EE * 120];

__device__ __forceinline__ ull pack2(float x, float y){ ull r; asm("mov.b64 %0,{%1,%2};":"=l"(r):"f"(x),"f"(y)); return r; }
__device__ __forceinline__ void unpack2(ull v, float&x, float&y){ asm("mov.b64 {%0,%1},%2;":"=f"(x),"=f"(y):"l"(v)); }
__device__ __forceinline__ void fma2(ull&d, ull a, ull b){ asm("fma.rn.f32x2 %0,%1,%2,%0;":"+l"(d):"l"(a),"l"(b)); }
__device__ __forceinline__ float4 ldg4(const float* p){ return __ldg(reinterpret_cast<const float4*>(p)); }
__device__ __forceinline__ void red4(float* p, float a, float b, float c, float d){
    asm volatile("red.global.add.v4.f32 [%0],{%1,%2,%3,%4};"::"l"(p),"f"(a),"f"(b),"f"(c),"f"(d):"memory");
}
__device__ __forceinline__ float wsum(float v){
    #pragma unroll
    for (int o=16;o;o>>=1) v += __shfl_xor_sync(0xffffffffu, v, o);
    return v;
}
__device__ __forceinline__ u32 f2tf32(float v){
    u32 t; asm("cvt.rna.tf32.f32 %0, %1;" : "=r"(t) : "f"(v)); return t;
}

// ---------------- mma.sync tf32 fragment helpers ----------------
// A-frag storage for one 128x8 ktile: [mti 0..7][lane][4] u32  (1024 words)
// value(row,k): a-reg r = (row%16>=8) + 2*((k%8)>=4), lane=((row%16)&7)*4+(k&3)
__device__ __forceinline__ void st_af(float* base, int row, int k, float v){
    int kt=k>>3, mti=row>>4, rm=row&15, kc=k&7;
    int r = ((rm>>3)&1) + ((kc>>2)<<1);
    int lane = (rm&7)*4 + (kc&3);
    reinterpret_cast<u32*>(base)[((kt*8+mti)*32+lane)*4 + r] = f2tf32(v);
}
// B slot (one ktile, 8k x 128n): [nti 0..15][lane][2] u32 (1024 words)
__device__ __forceinline__ void stage_bslots(float* bbase, const float* __restrict__ W,
                                             int kt0, int nkt, int Kreal, int tid){
    for (int idx=tid; idx<nkt*1024; idx+=256){
        int off = idx & 1023;
        int nti = off>>6, lane = (off>>1)&31, r = off&1;
        int n = nti*8 + (lane>>2);
        int k = (kt0 + (idx>>10))*8 + (lane&3) + 4*r;
        float v = (n<120 && k<Kreal) ? __ldg(W + (size_t)k*120 + n) : 0.f;
        reinterpret_cast<u32*>(bbase)[idx] = f2tf32(v);
    }
}

__device__ __forceinline__ void mma_tf32(float* c, u32 a0,u32 a1,u32 a2,u32 a3, u32 b0,u32 b1){
    asm volatile("mma.sync.aligned.m16n8k8.row.col.f32.tf32.tf32.f32 "
        "{%0,%1,%2,%3},{%4,%5,%6,%7},{%8,%9},{%0,%1,%2,%3};"
        : "+f"(c[0]),"+f"(c[1]),"+f"(c[2]),"+f"(c[3])
        : "r"(a0),"r"(a1),"r"(a2),"r"(a3),"r"(b0),"r"(b1));
}

// one k-step (k=8) over the warp's 64x32 tile
__device__ __forceinline__ void mma_step(const float* af, const float* bs,
                                         int wm, int wn, int lane, float acc[4][4][4]){
    u32 a[4][4], b[4][2];
    #pragma unroll
    for (int mt=0; mt<4; mt++){
        float4 v = *reinterpret_cast<const float4*>(af + ((size_t)((wm*4+mt)*32+lane))*4);
        a[mt][0]=__float_as_uint(v.x); a[mt][1]=__float_as_uint(v.y);
        a[mt][2]=__float_as_uint(v.z); a[mt][3]=__float_as_uint(v.w);
    }
    #pragma unroll
    for (int nt=0; nt<4; nt++){
        float2 v = *reinterpret_cast<const float2*>(bs + ((size_t)((wn*4+nt)*32+lane))*2);
        b[nt][0]=__float_as_uint(v.x); b[nt][1]=__float_as_uint(v.y);
    }
    #pragma unroll
    for (int mt=0; mt<4; mt++){
        #pragma unroll
        for (int nt=0; nt<4; nt++)
            mma_tf32(acc[mt][nt], a[mt][0],a[mt][1],a[mt][2],a[mt][3], b[nt][0],b[nt][1]);
    }
}

__device__ __forceinline__ void zero_acc(float acc[4][4][4]){
    #pragma unroll
    for (int i=0;i<4;i++){
        #pragma unroll
        for (int j=0;j<4;j++){
            #pragma unroll
            for (int r=0;r<4;r++) acc[i][j][r]=0.f;
        }
    }
}

// silu(acc + sb[col]) -> A-frag store
__device__ __forceinline__ void epilogue_h(float acc[4][4][4], const float* sb, float* hbase,
                                           int wm, int wn, int lane){
    int r0 = wm*64 + (lane>>2);
    int c0b = wn*32 + 2*(lane&3);
    #pragma unroll
    for (int mt=0; mt<4; mt++){
        int row0 = r0 + mt*16;
        #pragma unroll
        for (int nt=0; nt<4; nt++){
            int col0 = c0b + nt*8;
            #pragma unroll
            for (int ri=0; ri<4; ri++){
                int row = row0 + (ri>>1)*8;
                int col = col0 + (ri&1);
                if (col < 120){
                    float x = acc[mt][nt][ri] + sb[col];
                    st_af(hbase, row, col, x/(1.f+__expf(-x)));
                }
            }
        }
    }
}

// ---------- K0: residual init ----------
__global__ void init_out_kernel(const float* __restrict__ xs, const float* __restrict__ xe, float* __restrict__ out){
    size_t i = (size_t)blockIdx.x*blockDim.x + threadIdx.x;
    size_t ns = (size_t)NN*120, ne = (size_t)NN*240;
    if (i < ns) out[i] = xs[i];
    if (i < ne) out[ns + i] = xe[i];
}

// ---------- K1: node LayerNorm + O3 LayerNorm ----------
__global__ void node_norm_kernel(const float* __restrict__ xs_in, const float* __restrict__ xe_in,
                                 const float* __restrict__ lnw, const float* __restrict__ lnb,
                                 const float* __restrict__ o3w){
    int lane = threadIdx.x & 31;
    int node = blockIdx.x*4 + (threadIdx.x >> 5);
    if (node >= NN) return;
    const float* xs = xs_in + (size_t)node*120;
    float v0=xs[lane], v1=xs[lane+32], v2=xs[lane+64], v3=(lane<24)?xs[lane+96]:0.f;
    float s = wsum(v0+v1+v2+v3);
    float q = wsum(v0*v0+v1*v1+v2*v2+v3*v3);
    float mean = s*(1.f/120.f);
    float inv = rsqrtf(q*(1.f/120.f) - mean*mean + 1e-5f);
    float* ns = g_ns + (size_t)node*120;
    ns[lane]    = (v0-mean)*inv*__ldg(lnw+lane)    + __ldg(lnb+lane);
    ns[lane+32] = (v1-mean)*inv*__ldg(lnw+lane+32) + __ldg(lnb+lane+32);
    ns[lane+64] = (v2-mean)*inv*__ldg(lnw+lane+64) + __ldg(lnb+lane+64);
    if (lane<24) ns[lane+96] = (v3-mean)*inv*__ldg(lnw+lane+96) + __ldg(lnb+lane+96);

    const float* xe = xe_in + (size_t)node*240;
    float* ne = g_ne + (size_t)node*240;
    {
        float e0=xe[lane], e1=xe[lane+32];
        float m = wsum(e0+e1)*(1.f/64.f);
        float c0=e0-m, c1=e1-m;
        float r = rsqrtf(wsum(c0*c0+c1*c1)*(1.f/64.f) + 1e-5f);
        ne[lane]    = c0*r*__ldg(o3w+lane);
        ne[lane+32] = c1*r*__ldg(o3w+lane+32);
    }
    {
        float y0=xe[64+lane], y1=xe[96+lane], y2=xe[128+lane];
        float r = rsqrtf(wsum(y0*y0+y1*y1+y2*y2)*(1.f/96.f) + 1e-5f);
        ne[64+lane]  = y0*r*__ldg(o3w+64+(lane)/3);
        ne[96+lane]  = y1*r*__ldg(o3w+64+(32+lane)/3);
        ne[128+lane] = y2*r*__ldg(o3w+64+(64+lane)/3);
    }
    {
        float z0=xe[160+lane], z1=xe[192+lane], z2=(lane<16)?xe[224+lane]:0.f;
        float r = rsqrtf(wsum(z0*z0+z1*z1+z2*z2)*(1.f/80.f) + 1e-5f);
        ne[160+lane] = z0*r*__ldg(o3w+96+(lane)/5);
        ne[192+lane] = z1*r*__ldg(o3w+96+(32+lane)/5);
        if (lane<16) ne[224+lane] = z2*r*__ldg(o3w+96+(64+lane)/5);
    }
}

// ---------- K2: 6 projections in one launch (FFMA2 path) ----------
__device__ __forceinline__ void gemm_chunk(const float* __restrict__ Ash, const float* __restrict__ Bsh,
                                           int klen, int rt, int colBase, ull acc[4][8]){
    #pragma unroll 4
    for (int k=0;k<klen;k++){
        float4 a4 = *reinterpret_cast<const float4*>(Ash + k*132 + (rt<<2));
        ull ap0=pack2(a4.x,a4.x), ap1=pack2(a4.y,a4.y), ap2=pack2(a4.z,a4.z), ap3=pack2(a4.w,a4.w);
        const ulonglong2* bp = reinterpret_cast<const ulonglong2*>(Bsh + k*128 + colBase);
        ulonglong2 b01=bp[0], b23=bp[1], b45=bp[2], b67=bp[3];
        ull bb[8] = {b01.x,b01.y,b23.x,b23.y,b45.x,b45.y,b67.x,b67.y};
        #pragma unroll
        for (int j=0;j<8;j++){
            fma2(acc[0][j],ap0,bb[j]); fma2(acc[1][j],ap1,bb[j]);
            fma2(acc[2][j],ap2,bb[j]); fma2(acc[3][j],ap3,bb[j]);
        }
    }
}

__global__ __launch_bounds__(256) void proj_kernel(
    const float* __restrict__ W0, const float* __restrict__ W1, const float* __restrict__ W2,
    const float* __restrict__ W3, const float* __restrict__ W4, const float* __restrict__ W5)
{
    __shared__ alignas(16) float Bsh[32*128];
    __shared__ alignas(16) float Ash[32*132];
    int sel = blockIdx.y;
    const float* B = (sel==0)?W0:(sel==1)?W1:(sel==2)?W2:(sel==3)?W3:(sel==4)?W4:W5;
    float* C = (sel==0)?g_qinv:(sel==1)?g_kinv:(sel==2)?g_vinv:(sel==3)?g_qsph:(sel==4)?g_ksph:g_vsph;
    int ncols = (sel==5)?112:120;
    const float* A = g_ns;

    int tid = threadIdx.x;
    int ct = tid>>5, rt = tid&31;
    int rowBase = blockIdx.x*128, colBase = ct*16;
    ull acc[4][8];
    #pragma unroll
    for (int r=0;r<4;r++){
        #pragma unroll
        for (int j=0;j<8;j++) acc[r][j]=0ull;
    }
    for (int kc=0; kc<120; kc+=32){
        int klen = min(32, 120-kc);
        __syncthreads();
        for (int idx=tid; idx<klen*128; idx+=256){
            int k = idx>>7, j = idx&127;
            Bsh[idx] = (j<ncols) ? __ldg(B + (kc+k)*ncols + j) : 0.f;
        }
        for (int idx=tid; idx<128*klen; idx+=256){
            int row=idx/klen, kk=idx-row*klen;
            Ash[kk*132+row] = A[(size_t)(rowBase+row)*120 + kc+kk];
        }
        __syncthreads();
        gemm_chunk(Ash, Bsh, klen, rt, colBase, acc);
    }
    #pragma unroll
    for (int r=0;r<4;r++){
        int row = rowBase + rt*4 + r;
        #pragma unroll
        for (int j=0;j<8;j++){
            float lo,hi; unpack2(acc[r][j],lo,hi);
            int c0 = colBase + 2*j;
            if (c0   < ncols) C[(size_t)row*ncols + c0]   = lo;
            if (c0+1 < ncols) C[(size_t)row*ncols + c0+1] = hi;
        }
    }
}

// ---------- fused edge kernel on mma.sync tf32 ----------
// smem (floats): AF_H1 15 ktiles (d occupies first 14) | AF_H2 15 | AF_RBF 3 | BSLOT 8 | biases/fc
#define AF_H1  0
#define AF_H2  15360
#define AF_RBF 30720
#define BSLOT  33792
#define ESB1   41984
#define ESB2   42112
#define ESB3   42240
#define EFC    42368
#define EM_FLOATS 42496

__global__ __launch_bounds__(256,1) void edge_mma_kernel(
    const int* __restrict__ ei, const float* __restrict__ rbf, const float* __restrict__ fcut,
    const float* __restrict__ inv_w1, const float* __restrict__ inv_b1,
    const float* __restrict__ inv_w2, const float* __restrict__ inv_b2,
    const float* __restrict__ rbf_w1, const float* __restrict__ rbf_b1,
    const float* __restrict__ rbf_w2, const float* __restrict__ rbf_b2)
{
    extern __shared__ float sm[];
    int tid = threadIdx.x;
    int warp = tid>>5, lane = tid&31;
    int wm = warp>>2, wn = warp&3;
    int e0 = blockIdx.x * 128;

    // zero rbf A-frag pad (kt=2, kc 4..7 -> regs 2,3)
    for (int idx=tid; idx<512; idx+=256){
        int mti = idx>>6, rest = idx&63, ln = rest>>1, r = 2+(rest&1);
        sm[AF_RBF + ((2*8+mti)*32+ln)*4 + r] = 0.f;
    }
    if (tid < 128){
        sm[ESB1+tid] = (tid<120) ? __ldg(inv_b1+tid) : 0.f;
        sm[ESB2+tid] = (tid<120) ? __ldg(rbf_b1+tid) : 0.f;
        sm[ESB3+tid] = (tid<120) ? (__ldg(inv_b2+tid)+__ldg(rbf_b2+tid)) : 0.f;
        sm[EFC+tid]  = __ldg(fcut + e0 + tid);
    }
    // gather + equi_dot -> d A-frags (K=112 exactly)
    for (int el = warp; el < 128; el += 8){
        int e = e0 + el;
        int a_n = __ldg(ei+EE+e), b_n = __ldg(ei+e);
        const float* a = g_ne + (size_t)a_n*240;
        const float* b = g_ne + (size_t)b_n*240;
        { float d = __ldg(a+lane)-__ldg(b+lane);       st_af(sm+AF_H1, el, lane,    d*d); }
        { float d = __ldg(a+lane+32)-__ldg(b+lane+32); st_af(sm+AF_H1, el, lane+32, d*d); }
        { int base = 64 + lane*3; float s=0.f;
          #pragma unroll
          for (int j=0;j<3;j++){ float d=__ldg(a+base+j)-__ldg(b+base+j); s+=d*d; }
          st_af(sm+AF_H1, el, 64+lane, s); }
        if (lane<16){ int base = 160 + lane*5; float s=0.f;
          #pragma unroll
          for (int j=0;j<5;j++){ float d=__ldg(a+base+j)-__ldg(b+base+j); s+=d*d; }
          st_af(sm+AF_H1, el, 96+lane, s); }
    }
    // rbf A-frags (K=20 real, padded to 24)
    for (int idx=tid; idx<128*20; idx+=256){
        int row = idx/20, k = idx - row*20;
        st_af(sm+AF_RBF, row, k, __ldg(rbf + (size_t)(e0+row)*20 + k));
    }
    // rbf_w1 B-frags: ktiles 0..2
    stage_bslots(sm+BSLOT, rbf_w1, 0, 3, 20, tid);
    __syncthreads();

    float acc[4][4][4];
    zero_acc(acc);

    // GEMM2: rbf @ rbf_w1 (3 ksteps)
    #pragma unroll
    for (int kt=0; kt<3; kt++)
        mma_step(sm+AF_RBF+kt*1024, sm+BSLOT+kt*1024, wm, wn, lane, acc);
    __syncthreads();
    // h2 <- silu(acc + rbf_b1); reload slots with inv_w1 kt 0..7
    epilogue_h(acc, sm+ESB2, sm+AF_H2, wm, wn, lane);
    stage_bslots(sm+BSLOT, inv_w1, 0, 8, 112, tid);
    zero_acc(acc);
    __syncthreads();

    // GEMM1: d @ inv_w1 (14 ksteps)
    #pragma unroll
    for (int kt=0; kt<8; kt++)
        mma_step(sm+AF_H1+kt*1024, sm+BSLOT+kt*1024, wm, wn, lane, acc);
    __syncthreads();
    stage_bslots(sm+BSLOT, inv_w1, 8, 6, 112, tid);
    __syncthreads();
    #pragma unroll
    for (int kt=8; kt<14; kt++)
        mma_step(sm+AF_H1+kt*1024, sm+BSLOT+(kt-8)*1024, wm, wn, lane, acc);
    __syncthreads();   // all d reads complete before h1 overwrites AF_H1
    epilogue_h(acc, sm+ESB1, sm+AF_H1, wm, wn, lane);
    stage_bslots(sm+BSLOT, inv_w2, 0, 8, 120, tid);
    zero_acc(acc);
    __syncthreads();

    // GEMM3a: h1 @ inv_w2 (15 ksteps)
    #pragma unroll
    for (int kt=0; kt<8; kt++)
        mma_step(sm+AF_H1+kt*1024, sm+BSLOT+kt*1024, wm, wn, lane, acc);
    __syncthreads();
    stage_bslots(sm+BSLOT, inv_w2, 8, 7, 120, tid);
    __syncthreads();
    #pragma unroll
    for (int kt=8; kt<15; kt++)
        mma_step(sm+AF_H1+kt*1024, sm+BSLOT+(kt-8)*1024, wm, wn, lane, acc);
    __syncthreads();
    // GEMM3b: h2 @ rbf_w2 (15 ksteps, accumulate)
    stage_bslots(sm+BSLOT, rbf_w2, 0, 8, 120, tid);
    __syncthreads();
    #pragma unroll
    for (int kt=0; kt<8; kt++)
        mma_step(sm+AF_H2+kt*1024, sm+BSLOT+kt*1024, wm, wn, lane, acc);
    __syncthreads();
    stage_bslots(sm+BSLOT, rbf_w2, 8, 7, 120, tid);
    __syncthreads();
    #pragma unroll
    for (int kt=8; kt<15; kt++)
        mma_step(sm+AF_H2+kt*1024, sm+BSLOT+(kt-8)*1024, wm, wn, lane, acc);

    // final epilogue: w = (acc + b) * fcut -> g_w (float2 stores)
    {
        int r0 = wm*64 + (lane>>2);
        int c0b = wn*32 + 2*(lane&3);
        #pragma unroll
        for (int mt=0; mt<4; mt++){
            int rowA = r0 + mt*16;
            float fA = sm[EFC+rowA], fB = sm[EFC+rowA+8];
            #pragma unroll
            for (int nt=0; nt<4; nt++){
                int col0 = c0b + nt*8;
                if (col0 < 120){
                    float2 va, vb;
                    va.x = (acc[mt][nt][0] + sm[ESB3+col0])  *fA;
                    va.y = (acc[mt][nt][1] + sm[ESB3+col0+1])*fA;
                    vb.x = (acc[mt][nt][2] + sm[ESB3+col0])  *fB;
                    vb.y = (acc[mt][nt][3] + sm[ESB3+col0+1])*fB;
                    *reinterpret_cast<float2*>(g_w + (size_t)(e0+rowA)*120   + col0) = va;
                    *reinterpret_cast<float2*>(g_w + (size_t)(e0+rowA+8)*120 + col0) = vb;
                }
            }
        }
    }
}

// ---------- K6: attention + gated messages + scatter ----------
__global__ __launch_bounds__(256) void edge_attn_kernel(const int* __restrict__ ei,
                                                        const float* __restrict__ fcut,
                                                        const float* __restrict__ rsh,
                                                        float* __restrict__ outS,
                                                        float* __restrict__ outE){
    __shared__ float sgate[8][116];
    int warp = threadIdx.x>>5, lane = threadIdx.x&31;
    int e = blockIdx.x*8 + warp;
    int ct = __ldg(ei+e), nb = __ldg(ei+EE+e);
    float fc = __ldg(fcut+e);
    const float* w  = g_w   + (size_t)e*120;
    const float* qi = g_qinv + (size_t)ct*120;
    const float* ki = g_kinv + (size_t)nb*120;
    const float* vi = g_vinv + (size_t)nb*120;
    const float* qs = g_qsph + (size_t)ct*120;
    const float* ks = g_ksph + (size_t)nb*120;
    const float* vs = g_vsph + (size_t)nb*112;

    float s0=0,s1=0,s2=0,s3=0,t0=0,t1=0,t2=0;
    if (lane < 30){
        float4 wv = ldg4(w + 4*lane);
        float4 q  = ldg4(qi + 4*lane), k = ldg4(ki + 4*lane);
        float4 qe = ldg4(qs + 4*lane), ke = ldg4(ks + 4*lane);
        float wa[4]={wv.x,wv.y,wv.z,wv.w};
        float pa[4]={q.x*k.x, q.y*k.y, q.z*k.z, q.w*k.w};
        float pe[4]={qe.x*ke.x, qe.y*ke.y, qe.z*ke.z, qe.w*ke.w};
        #pragma unroll
        for (int j=0;j<4;j++){
            int idx = 4*lane + j;
            float p = wa[j]*pa[j];
            float pq = wa[j]*pe[j];
            int h = idx/30, l = idx/40;
            s0 += (h==0)?p:0.f; s1 += (h==1)?p:0.f; s2 += (h==2)?p:0.f; s3 += (h==3)?p:0.f;
            t0 += (l==0)?pq:0.f; t1 += (l==1)?pq:0.f; t2 += (l==2)?pq:0.f;
        }
    }
    const float SC_S = 0.091287092917527686f;
    const float SC_E = 0.094491118252306805f;
    s0 = wsum(s0)*SC_S; s1 = wsum(s1)*SC_S; s2 = wsum(s2)*SC_S; s3 = wsum(s3)*SC_S;
    t0 = wsum(t0)*SC_E; t1 = wsum(t1)*SC_E; t2 = wsum(t2)*SC_E;

    if (lane < 30){
        float4 v = ldg4(vi + 4*lane);
        float va[4]={v.x,v.y,v.z,v.w}, m[4];
        #pragma unroll
        for (int j=0;j<4;j++){
            int h = (4*lane+j)/30;
            float ss = (h==0)?s0:((h==1)?s1:((h==2)?s2:s3));
            m[j] = ss*va[j];
        }
        red4(outS + (size_t)ct*120 + 4*lane, m[0],m[1],m[2],m[3]);
    }
    if (lane < 28){
        float4 v = ldg4(vs + 4*lane);
        float va[4]={v.x,v.y,v.z,v.w};
        #pragma unroll
        for (int j=0;j<4;j++){
            int ir = 4*lane + j;
            float tl = (ir<64)?t0:((ir<96)?t1:t2);
            sgate[warp][ir] = tl*va[j]*fc;
        }
    }
    __syncwarp();
    if (lane < 30){
        int base = 8*lane;
        float4 r0 = ldg4(rsh + (size_t)e*240 + base);
        float4 r1 = ldg4(rsh + (size_t)e*240 + base + 4);
        float ra[8]={r0.x,r0.y,r0.z,r0.w,r1.x,r1.y,r1.z,r1.w}, m[8];
        #pragma unroll
        for (int j=0;j<8;j++){
            int c = base + j;
            int ir = (c<64)? c : (c<160)? 64+(c-64)/3 : 96+(c-160)/5;
            m[j] = ra[j]*sgate[warp][ir];
        }
        red4(outE + (size_t)ct*240 + base,     m[0],m[1],m[2],m[3]);
        red4(outE + (size_t)ct*240 + base + 4, m[4],m[5],m[6],m[7]);
    }
}

extern "C" void kernel_launch(void* const* d_in, const int* in_sizes, int n_in,
                              void* d_out, int out_size){
    const float* node_scalar=(const float*)d_in[0];
    const float* node_equi  =(const float*)d_in[1];
    const float* rbf        =(const float*)d_in[2];
    const float* fcut       =(const float*)d_in[3];
    const float* rsh        =(const float*)d_in[4];
    const float* ln_w =(const float*)d_in[5];
    const float* ln_b =(const float*)d_in[6];
    const float* o3w  =(const float*)d_in[7];
    const float* Wq   =(const float*)d_in[8];
    const float* Wk   =(const float*)d_in[9];
    const float* Wv   =(const float*)d_in[10];
    const float* Wqs  =(const float*)d_in[11];
    const float* Wks  =(const float*)d_in[12];
    const float* Wvs  =(const float*)d_in[13];
    const float* rbf_w1=(const float*)d_in[14];
    const float* rbf_b1=(const float*)d_in[15];
    const float* rbf_w2=(const float*)d_in[16];
    const float* rbf_b2=(const float*)d_in[17];
    const float* inv_w1=(const float*)d_in[18];
    const float* inv_b1=(const float*)d_in[19];
    const float* inv_w2=(const float*)d_in[20];
    const float* inv_b2=(const float*)d_in[21];
    const int*   ei    =(const int*)d_in[22];

    float* outS = (float*)d_out;
    float* outE = outS + (size_t)NN*120;

    cudaFuncSetAttribute(edge_mma_kernel, cudaFuncAttributeMaxDynamicSharedMemorySize, EM_FLOATS*4);

    init_out_kernel<<<(NN*240 + 255)/256, 256>>>(node_scalar, node_equi, (float*)d_out);
    node_norm_kernel<<<NN/4, 128>>>(node_scalar, node_equi, ln_w, ln_b, o3w);
    proj_kernel<<<dim3(NN/128, 6), 256>>>(Wq, Wk, Wv, Wqs, Wks, Wvs);
    edge_mma_kernel<<<EE/128, 256, EM_FLOATS*4>>>(ei, rbf, fcut,
        inv_w1, inv_b1, inv_w2, inv_b2, rbf_w1, rbf_b1, rbf_w2, rbf_b2);
    edge_attn_kernel<<<EE/8, 256>>>(ei, fcut, rsh, outS, outE);
}

// round 8
// speedup vs baseline: 2.4269x; 1.6827x over previous
#include <cuda_runtime.h>
#include <math.h>

#define NN 16384
#define EE 262144
typedef unsigned long long ull;
typedef unsigned int u32;

__device__ float g_ns  [NN * 120];
__device__ float g_ne  [NN * 240];
__device__ float g_qinv[NN * 120];
__device__ float g_kinv[NN * 120];
__device__ float g_vinv[NN * 120];
__device__ float g_qsph[NN * 120];
__device__ float g_ksph[NN * 120];
__device__ float g_vsph[NN * 112];
__device__ float g_w   [(size_t)EE * 120];
// fragment-layout tf32 weights: [(kt*16+nti)*32+lane]*2 + r
__device__ u32 g_w1f [14*1024];
__device__ u32 g_wr1f[ 3*1024];
__device__ u32 g_w2f [15*1024];
__device__ u32 g_wr2f[15*1024];

__device__ __forceinline__ ull pack2(float x, float y){ ull r; asm("mov.b64 %0,{%1,%2};":"=l"(r):"f"(x),"f"(y)); return r; }
__device__ __forceinline__ void unpack2(ull v, float&x, float&y){ asm("mov.b64 {%0,%1},%2;":"=f"(x),"=f"(y):"l"(v)); }
__device__ __forceinline__ void fma2(ull&d, ull a, ull b){ asm("fma.rn.f32x2 %0,%1,%2,%0;":"+l"(d):"l"(a),"l"(b)); }
__device__ __forceinline__ float4 ldg4(const float* p){ return __ldg(reinterpret_cast<const float4*>(p)); }
__device__ __forceinline__ void red4(float* p, float a, float b, float c, float d){
    asm volatile("red.global.add.v4.f32 [%0],{%1,%2,%3,%4};"::"l"(p),"f"(a),"f"(b),"f"(c),"f"(d):"memory");
}
__device__ __forceinline__ float wsum(float v){
    #pragma unroll
    for (int o=16;o;o>>=1) v += __shfl_xor_sync(0xffffffffu, v, o);
    return v;
}
__device__ __forceinline__ u32 f2tf32(float v){
    u32 t; asm("cvt.rna.tf32.f32 %0, %1;" : "=r"(t) : "f"(v)); return t;
}
__device__ __forceinline__ void mma_tf32(float* c, u32 a0,u32 a1,u32 a2,u32 a3, u32 b0,u32 b1){
    asm volatile("mma.sync.aligned.m16n8k8.row.col.f32.tf32.tf32.f32 "
        "{%0,%1,%2,%3},{%4,%5,%6,%7},{%8,%9},{%0,%1,%2,%3};"
        : "+f"(c[0]),"+f"(c[1]),"+f"(c[2]),"+f"(c[3])
        : "r"(a0),"r"(a1),"r"(a2),"r"(a3),"r"(b0),"r"(b1));
}

// A-frag (64 rows x 8k per ktile): ((kt*4+mti)*32+lane)*4 + r
__device__ __forceinline__ void st_af(float* base, int row, int k, float v){
    int kt=k>>3, mti=row>>4, rm=row&15, kc=k&7;
    int r = ((rm>>3)&1) + ((kc>>2)<<1);
    int lane = (rm&7)*4 + (kc&3);
    reinterpret_cast<u32*>(base)[((kt*4+mti)*32+lane)*4 + r] = f2tf32(v);
}

// one k-step over warp's 32x32 tile; B fragments straight from gmem (L2)
__device__ __forceinline__ void mma_step(const float* af, const u32* __restrict__ bw,
                                         int kt, int wm, int lane, float acc[2][4][4]){
    u32 a[2][4], b[4][2];
    #pragma unroll
    for (int nt=0; nt<4; nt++){
        uint2 v = __ldg(reinterpret_cast<const uint2*>(bw + kt*1024 + nt*64));
        b[nt][0]=v.x; b[nt][1]=v.y;
    }
    #pragma unroll
    for (int mt=0; mt<2; mt++){
        float4 v = *reinterpret_cast<const float4*>(af + ((size_t)((kt*4 + wm*2+mt)*32+lane))*4);
        a[mt][0]=__float_as_uint(v.x); a[mt][1]=__float_as_uint(v.y);
        a[mt][2]=__float_as_uint(v.z); a[mt][3]=__float_as_uint(v.w);
    }
    #pragma unroll
    for (int mt=0; mt<2; mt++){
        #pragma unroll
        for (int nt=0; nt<4; nt++)
            mma_tf32(acc[mt][nt], a[mt][0],a[mt][1],a[mt][2],a[mt][3], b[nt][0],b[nt][1]);
    }
}

__device__ __forceinline__ void zero_acc(float acc[2][4][4]){
    #pragma unroll
    for (int i=0;i<2;i++){
        #pragma unroll
        for (int j=0;j<4;j++){
            #pragma unroll
            for (int r=0;r<4;r++) acc[i][j][r]=0.f;
        }
    }
}

// silu(acc + sb[col]) -> A-frag store
__device__ __forceinline__ void epilogue_h(float acc[2][4][4], const float* sb, float* hbase,
                                           int wm, int wn, int lane){
    int r0 = wm*32 + (lane>>2);
    int c0b = wn*32 + 2*(lane&3);
    #pragma unroll
    for (int mt=0; mt<2; mt++){
        int row0 = r0 + mt*16;
        #pragma unroll
        for (int nt=0; nt<4; nt++){
            int col0 = c0b + nt*8;
            #pragma unroll
            for (int ri=0; ri<4; ri++){
                int row = row0 + (ri>>1)*8;
                int col = col0 + (ri&1);
                if (col < 120){
                    float x = acc[mt][nt][ri] + sb[col];
                    st_af(hbase, row, col, x/(1.f+__expf(-x)));
                }
            }
        }
    }
}

// ---------- setup: convert weights to fragment-layout tf32 ----------
__global__ void conv_weights_kernel(const float* __restrict__ inv_w1, const float* __restrict__ rbf_w1,
                                    const float* __restrict__ inv_w2, const float* __restrict__ rbf_w2){
    int idx = blockIdx.x*256 + threadIdx.x;
    if (idx >= 48128) return;
    const float* W; u32* O; int K, l;
    if (idx < 14336){ W=inv_w1; O=g_w1f;  K=112; l=idx; }
    else if (idx < 17408){ W=rbf_w1; O=g_wr1f; K=20; l=idx-14336; }
    else if (idx < 32768){ W=inv_w2; O=g_w2f;  K=120; l=idx-17408; }
    else { W=rbf_w2; O=g_wr2f; K=120; l=idx-32768; }
    int kt = l>>10, rest = l&1023;
    int nti = rest>>6, lane=(rest>>1)&31, r = rest&1;
    int n = nti*8 + (lane>>2);
    int k = kt*8 + (lane&3) + 4*r;
    float v = (n<120 && k<K) ? __ldg(W + (size_t)k*120 + n) : 0.f;
    O[l] = f2tf32(v);
}

// ---------- K0: residual init ----------
__global__ void init_out_kernel(const float* __restrict__ xs, const float* __restrict__ xe, float* __restrict__ out){
    size_t i = (size_t)blockIdx.x*blockDim.x + threadIdx.x;
    size_t ns = (size_t)NN*120, ne = (size_t)NN*240;
    if (i < ns) out[i] = xs[i];
    if (i < ne) out[ns + i] = xe[i];
}

// ---------- K1: node LayerNorm + O3 LayerNorm ----------
__global__ void node_norm_kernel(const float* __restrict__ xs_in, const float* __restrict__ xe_in,
                                 const float* __restrict__ lnw, const float* __restrict__ lnb,
                                 const float* __restrict__ o3w){
    int lane = threadIdx.x & 31;
    int node = blockIdx.x*4 + (threadIdx.x >> 5);
    if (node >= NN) return;
    const float* xs = xs_in + (size_t)node*120;
    float v0=xs[lane], v1=xs[lane+32], v2=xs[lane+64], v3=(lane<24)?xs[lane+96]:0.f;
    float s = wsum(v0+v1+v2+v3);
    float q = wsum(v0*v0+v1*v1+v2*v2+v3*v3);
    float mean = s*(1.f/120.f);
    float inv = rsqrtf(q*(1.f/120.f) - mean*mean + 1e-5f);
    float* ns = g_ns + (size_t)node*120;
    ns[lane]    = (v0-mean)*inv*__ldg(lnw+lane)    + __ldg(lnb+lane);
    ns[lane+32] = (v1-mean)*inv*__ldg(lnw+lane+32) + __ldg(lnb+lane+32);
    ns[lane+64] = (v2-mean)*inv*__ldg(lnw+lane+64) + __ldg(lnb+lane+64);
    if (lane<24) ns[lane+96] = (v3-mean)*inv*__ldg(lnw+lane+96) + __ldg(lnb+lane+96);

    const float* xe = xe_in + (size_t)node*240;
    float* ne = g_ne + (size_t)node*240;
    {
        float e0=xe[lane], e1=xe[lane+32];
        float m = wsum(e0+e1)*(1.f/64.f);
        float c0=e0-m, c1=e1-m;
        float r = rsqrtf(wsum(c0*c0+c1*c1)*(1.f/64.f) + 1e-5f);
        ne[lane]    = c0*r*__ldg(o3w+lane);
        ne[lane+32] = c1*r*__ldg(o3w+lane+32);
    }
    {
        float y0=xe[64+lane], y1=xe[96+lane], y2=xe[128+lane];
        float r = rsqrtf(wsum(y0*y0+y1*y1+y2*y2)*(1.f/96.f) + 1e-5f);
        ne[64+lane]  = y0*r*__ldg(o3w+64+(lane)/3);
        ne[96+lane]  = y1*r*__ldg(o3w+64+(32+lane)/3);
        ne[128+lane] = y2*r*__ldg(o3w+64+(64+lane)/3);
    }
    {
        float z0=xe[160+lane], z1=xe[192+lane], z2=(lane<16)?xe[224+lane]:0.f;
        float r = rsqrtf(wsum(z0*z0+z1*z1+z2*z2)*(1.f/80.f) + 1e-5f);
        ne[160+lane] = z0*r*__ldg(o3w+96+(lane)/5);
        ne[192+lane] = z1*r*__ldg(o3w+96+(32+lane)/5);
        if (lane<16) ne[224+lane] = z2*r*__ldg(o3w+96+(64+lane)/5);
    }
}

// ---------- K2: 6 projections in one launch (FFMA2 path) ----------
__device__ __forceinline__ void gemm_chunk(const float* __restrict__ Ash, const float* __restrict__ Bsh,
                                           int klen, int rt, int colBase, ull acc[4][8]){
    #pragma unroll 4
    for (int k=0;k<klen;k++){
        float4 a4 = *reinterpret_cast<const float4*>(Ash + k*132 + (rt<<2));
        ull ap0=pack2(a4.x,a4.x), ap1=pack2(a4.y,a4.y), ap2=pack2(a4.z,a4.z), ap3=pack2(a4.w,a4.w);
        const ulonglong2* bp = reinterpret_cast<const ulonglong2*>(Bsh + k*128 + colBase);
        ulonglong2 b01=bp[0], b23=bp[1], b45=bp[2], b67=bp[3];
        ull bb[8] = {b01.x,b01.y,b23.x,b23.y,b45.x,b45.y,b67.x,b67.y};
        #pragma unroll
        for (int j=0;j<8;j++){
            fma2(acc[0][j],ap0,bb[j]); fma2(acc[1][j],ap1,bb[j]);
            fma2(acc[2][j],ap2,bb[j]); fma2(acc[3][j],ap3,bb[j]);
        }
    }
}

__global__ __launch_bounds__(256) void proj_kernel(
    const float* __restrict__ W0, const float* __restrict__ W1, const float* __restrict__ W2,
    const float* __restrict__ W3, const float* __restrict__ W4, const float* __restrict__ W5)
{
    __shared__ alignas(16) float Bsh[32*128];
    __shared__ alignas(16) float Ash[32*132];
    int sel = blockIdx.y;
    const float* B = (sel==0)?W0:(sel==1)?W1:(sel==2)?W2:(sel==3)?W3:(sel==4)?W4:W5;
    float* C = (sel==0)?g_qinv:(sel==1)?g_kinv:(sel==2)?g_vinv:(sel==3)?g_qsph:(sel==4)?g_ksph:g_vsph;
    int ncols = (sel==5)?112:120;
    const float* A = g_ns;

    int tid = threadIdx.x;
    int ct = tid>>5, rt = tid&31;
    int rowBase = blockIdx.x*128, colBase = ct*16;
    ull acc[4][8];
    #pragma unroll
    for (int r=0;r<4;r++){
        #pragma unroll
        for (int j=0;j<8;j++) acc[r][j]=0ull;
    }
    for (int kc=0; kc<120; kc+=32){
        int klen = min(32, 120-kc);
        __syncthreads();
        for (int idx=tid; idx<klen*128; idx+=256){
            int k = idx>>7, j = idx&127;
            Bsh[idx] = (j<ncols) ? __ldg(B + (kc+k)*ncols + j) : 0.f;
        }
        for (int idx=tid; idx<128*klen; idx+=256){
            int row=idx/klen, kk=idx-row*klen;
            Ash[kk*132+row] = A[(size_t)(rowBase+row)*120 + kc+kk];
        }
        __syncthreads();
        gemm_chunk(Ash, Bsh, klen, rt, colBase, acc);
    }
    #pragma unroll
    for (int r=0;r<4;r++){
        int row = rowBase + rt*4 + r;
        #pragma unroll
        for (int j=0;j<8;j++){
            float lo,hi; unpack2(acc[r][j],lo,hi);
            int c0 = colBase + 2*j;
            if (c0   < ncols) C[(size_t)row*ncols + c0]   = lo;
            if (c0+1 < ncols) C[(size_t)row*ncols + c0+1] = hi;
        }
    }
}

// ---------- fused edge kernel: 64-edge tiles, B fragments from L2 ----------
// smem floats: AF1 15*512 | AF2 15*512 | AFR 3*512 | SB1/SB2/SB3 128 | FC 64
#define AF1X 0
#define AF2X 7680
#define AFRX 15360
#define XSB1 16896
#define XSB2 17024
#define XSB3 17152
#define XFC  17280
#define EM_FLOATS 17344

__global__ __launch_bounds__(256,3) void edge_mma_kernel(
    const int* __restrict__ ei, const float* __restrict__ rbf, const float* __restrict__ fcut,
    const float* __restrict__ inv_b1, const float* __restrict__ inv_b2,
    const float* __restrict__ rbf_b1, const float* __restrict__ rbf_b2)
{
    extern __shared__ float sm[];
    int tid = threadIdx.x;
    int warp = tid>>5, lane = tid&31;
    int wm = warp>>2, wn = warp&3;
    int e0 = blockIdx.x * 64;

    // per-warp B pointers (fragment layout)
    int boff = (wn*4)*64 + lane*2;
    const u32* bw1  = g_w1f  + boff;
    const u32* bwr1 = g_wr1f + boff;
    const u32* bw2  = g_w2f  + boff;
    const u32* bwr2 = g_wr2f + boff;

    // zero rbf A-frag pad (kt=2, regs 2..3)
    for (int idx=tid; idx<256; idx+=256){
        int mti = idx>>6, rest = idx&63, ln = rest>>1, r = 2+(rest&1);
        sm[AFRX + ((2*4+mti)*32+ln)*4 + r] = 0.f;
    }
    if (tid < 128){
        sm[XSB1+tid] = (tid<120) ? __ldg(inv_b1+tid) : 0.f;
        sm[XSB2+tid] = (tid<120) ? __ldg(rbf_b1+tid) : 0.f;
        sm[XSB3+tid] = (tid<120) ? (__ldg(inv_b2+tid)+__ldg(rbf_b2+tid)) : 0.f;
    }
    if (tid < 64) sm[XFC+tid] = __ldg(fcut + e0 + tid);

    // gather + equi_dot -> d A-frags (K=112)
    for (int el = warp; el < 64; el += 8){
        int e = e0 + el;
        int a_n = __ldg(ei+EE+e), b_n = __ldg(ei+e);
        const float* a = g_ne + (size_t)a_n*240;
        const float* b = g_ne + (size_t)b_n*240;
        { float d = __ldg(a+lane)-__ldg(b+lane);       st_af(sm+AF1X, el, lane,    d*d); }
        { float d = __ldg(a+lane+32)-__ldg(b+lane+32); st_af(sm+AF1X, el, lane+32, d*d); }
        { int base = 64 + lane*3; float s=0.f;
          #pragma unroll
          for (int j=0;j<3;j++){ float d=__ldg(a+base+j)-__ldg(b+base+j); s+=d*d; }
          st_af(sm+AF1X, el, 64+lane, s); }
        if (lane<16){ int base = 160 + lane*5; float s=0.f;
          #pragma unroll
          for (int j=0;j<5;j++){ float d=__ldg(a+base+j)-__ldg(b+base+j); s+=d*d; }
          st_af(sm+AF1X, el, 96+lane, s); }
    }
    // rbf A-frags (K=20)
    for (int idx=tid; idx<64*20; idx+=256){
        int row = idx/20, k = idx - row*20;
        st_af(sm+AFRX, row, k, __ldg(rbf + (size_t)(e0+row)*20 + k));
    }
    __syncthreads();   // A: staging complete

    float acc[2][4][4];
    zero_acc(acc);

    // GEMM2: rbf @ rbf_w1 (3 ksteps)
    #pragma unroll
    for (int kt=0; kt<3; kt++) mma_step(sm+AFRX, bwr1, kt, wm, lane, acc);
    epilogue_h(acc, sm+XSB2, sm+AF2X, wm, wn, lane);   // h2 -> AF2 (own cells)
    zero_acc(acc);

    // GEMM1: d @ inv_w1 (14 ksteps) — reads AF1, unchanged since sync A
    #pragma unroll
    for (int kt=0; kt<14; kt++) mma_step(sm+AF1X, bw1, kt, wm, lane, acc);
    __syncthreads();   // B: all d reads + h2 writes complete
    epilogue_h(acc, sm+XSB1, sm+AF1X, wm, wn, lane);   // h1 overwrites d
    zero_acc(acc);
    __syncthreads();   // C: h1/h2 visible to all

    // GEMM3: h1 @ inv_w2 + h2 @ rbf_w2 (15+15 ksteps)
    #pragma unroll
    for (int kt=0; kt<15; kt++) mma_step(sm+AF1X, bw2,  kt, wm, lane, acc);
    #pragma unroll
    for (int kt=0; kt<15; kt++) mma_step(sm+AF2X, bwr2, kt, wm, lane, acc);

    // final epilogue: w = (acc + b) * fcut -> g_w
    {
        int r0 = wm*32 + (lane>>2);
        int c0b = wn*32 + 2*(lane&3);
        #pragma unroll
        for (int mt=0; mt<2; mt++){
            int rowA = r0 + mt*16;
            float fA = sm[XFC+rowA], fB = sm[XFC+rowA+8];
            #pragma unroll
            for (int nt=0; nt<4; nt++){
                int col0 = c0b + nt*8;
                if (col0 < 120){
                    float2 va, vb;
                    va.x = (acc[mt][nt][0] + sm[XSB3+col0])  *fA;
                    va.y = (acc[mt][nt][1] + sm[XSB3+col0+1])*fA;
                    vb.x = (acc[mt][nt][2] + sm[XSB3+col0])  *fB;
                    vb.y = (acc[mt][nt][3] + sm[XSB3+col0+1])*fB;
                    *reinterpret_cast<float2*>(g_w + (size_t)(e0+rowA)*120   + col0) = va;
                    *reinterpret_cast<float2*>(g_w + (size_t)(e0+rowA+8)*120 + col0) = vb;
                }
            }
        }
    }
}

// ---------- K6: attention + gated messages + scatter ----------
__global__ __launch_bounds__(256) void edge_attn_kernel(const int* __restrict__ ei,
                                                        const float* __restrict__ fcut,
                                                        const float* __restrict__ rsh,
                                                        float* __restrict__ outS,
                                                        float* __restrict__ outE){
    __shared__ float sgate[8][116];
    int warp = threadIdx.x>>5, lane = threadIdx.x&31;
    int e = blockIdx.x*8 + warp;
    int ct = __ldg(ei+e), nb = __ldg(ei+EE+e);
    float fc = __ldg(fcut+e);
    const float* w  = g_w   + (size_t)e*120;
    const float* qi = g_qinv + (size_t)ct*120;
    const float* ki = g_kinv + (size_t)nb*120;
    const float* vi = g_vinv + (size_t)nb*120;
    const float* qs = g_qsph + (size_t)ct*120;
    const float* ks = g_ksph + (size_t)nb*120;
    const float* vs = g_vsph + (size_t)nb*112;

    float s0=0,s1=0,s2=0,s3=0,t0=0,t1=0,t2=0;
    if (lane < 30){
        float4 wv = ldg4(w + 4*lane);
        float4 q  = ldg4(qi + 4*lane), k = ldg4(ki + 4*lane);
        float4 qe = ldg4(qs + 4*lane), ke = ldg4(ks + 4*lane);
        float wa[4]={wv.x,wv.y,wv.z,wv.w};
        float pa[4]={q.x*k.x, q.y*k.y, q.z*k.z, q.w*k.w};
        float pe[4]={qe.x*ke.x, qe.y*ke.y, qe.z*ke.z, qe.w*ke.w};
        #pragma unroll
        for (int j=0;j<4;j++){
            int idx = 4*lane + j;
            float p = wa[j]*pa[j];
            float pq = wa[j]*pe[j];
            int h = idx/30, l = idx/40;
            s0 += (h==0)?p:0.f; s1 += (h==1)?p:0.f; s2 += (h==2)?p:0.f; s3 += (h==3)?p:0.f;
            t0 += (l==0)?pq:0.f; t1 += (l==1)?pq:0.f; t2 += (l==2)?pq:0.f;
        }
    }
    const float SC_S = 0.091287092917527686f;
    const float SC_E = 0.094491118252306805f;
    s0 = wsum(s0)*SC_S; s1 = wsum(s1)*SC_S; s2 = wsum(s2)*SC_S; s3 = wsum(s3)*SC_S;
    t0 = wsum(t0)*SC_E; t1 = wsum(t1)*SC_E; t2 = wsum(t2)*SC_E;

    if (lane < 30){
        float4 v = ldg4(vi + 4*lane);
        float va[4]={v.x,v.y,v.z,v.w}, m[4];
        #pragma unroll
        for (int j=0;j<4;j++){
            int h = (4*lane+j)/30;
            float ss = (h==0)?s0:((h==1)?s1:((h==2)?s2:s3));
            m[j] = ss*va[j];
        }
        red4(outS + (size_t)ct*120 + 4*lane, m[0],m[1],m[2],m[3]);
    }
    if (lane < 28){
        float4 v = ldg4(vs + 4*lane);
        float va[4]={v.x,v.y,v.z,v.w};
        #pragma unroll
        for (int j=0;j<4;j++){
            int ir = 4*lane + j;
            float tl = (ir<64)?t0:((ir<96)?t1:t2);
            sgate[warp][ir] = tl*va[j]*fc;
        }
    }
    __syncwarp();
    if (lane < 30){
        int base = 8*lane;
        float4 r0 = ldg4(rsh + (size_t)e*240 + base);
        float4 r1 = ldg4(rsh + (size_t)e*240 + base + 4);
        float ra[8]={r0.x,r0.y,r0.z,r0.w,r1.x,r1.y,r1.z,r1.w}, m[8];
        #pragma unroll
        for (int j=0;j<8;j++){
            int c = base + j;
            int ir = (c<64)? c : (c<160)? 64+(c-64)/3 : 96+(c-160)/5;
            m[j] = ra[j]*sgate[warp][ir];
        }
        red4(outE + (size_t)ct*240 + base,     m[0],m[1],m[2],m[3]);
        red4(outE + (size_t)ct*240 + base + 4, m[4],m[5],m[6],m[7]);
    }
}

extern "C" void kernel_launch(void* const* d_in, const int* in_sizes, int n_in,
                              void* d_out, int out_size){
    const float* node_scalar=(const float*)d_in[0];
    const float* node_equi  =(const float*)d_in[1];
    const float* rbf        =(const float*)d_in[2];
    const float* fcut       =(const float*)d_in[3];
    const float* rsh        =(const float*)d_in[4];
    const float* ln_w =(const float*)d_in[5];
    const float* ln_b =(const float*)d_in[6];
    const float* o3w  =(const float*)d_in[7];
    const float* Wq   =(const float*)d_in[8];
    const float* Wk   =(const float*)d_in[9];
    const float* Wv   =(const float*)d_in[10];
    const float* Wqs  =(const float*)d_in[11];
    const float* Wks  =(const float*)d_in[12];
    const float* Wvs  =(const float*)d_in[13];
    const float* rbf_w1=(const float*)d_in[14];
    const float* rbf_b1=(const float*)d_in[15];
    const float* rbf_w2=(const float*)d_in[16];
    const float* rbf_b2=(const float*)d_in[17];
    const float* inv_w1=(const float*)d_in[18];
    const float* inv_b1=(const float*)d_in[19];
    const float* inv_w2=(const float*)d_in[20];
    const float* inv_b2=(const float*)d_in[21];
    const int*   ei    =(const int*)d_in[22];

    float* outS = (float*)d_out;
    float* outE = outS + (size_t)NN*120;

    cudaFuncSetAttribute(edge_mma_kernel, cudaFuncAttributeMaxDynamicSharedMemorySize, EM_FLOATS*4);

    conv_weights_kernel<<<188, 256>>>(inv_w1, rbf_w1, inv_w2, rbf_w2);
    init_out_kernel<<<(NN*240 + 255)/256, 256>>>(node_scalar, node_equi, (float*)d_out);
    node_norm_kernel<<<NN/4, 128>>>(node_scalar, node_equi, ln_w, ln_b, o3w);
    proj_kernel<<<dim3(NN/128, 6), 256>>>(Wq, Wk, Wv, Wqs, Wks, Wvs);
    edge_mma_kernel<<<EE/64, 256, EM_FLOATS*4>>>(ei, rbf, fcut, inv_b1, inv_b2, rbf_b1, rbf_b2);
    edge_attn_kernel<<<EE/8, 256>>>(ei, fcut, rsh, outS, outE);
}

// round 9
// speedup vs baseline: 3.1971x; 1.3173x over previous
#include <cuda_runtime.h>
#include <math.h>

#define NN 16384
#define EE 262144
typedef unsigned long long ull;
typedef unsigned int u32;

__device__ float g_ns  [NN * 120];
__device__ float g_ne  [NN * 240];
__device__ float g_qinv[NN * 120];
__device__ float g_kinv[NN * 120];
__device__ float g_vinv[NN * 120];
__device__ float g_qsph[NN * 120];
__device__ float g_ksph[NN * 120];
__device__ float g_vsph[NN * 112];
__device__ float g_w   [(size_t)EE * 120];
// fragment-layout tf32 weights, 15360 words per weight:
// wid 0=inv_w1 1=rbf_w1 2=inv_w2 3=rbf_w2 4=Wq 5=Wk 6=Wv 7=Wqs 8=Wks 9=Wvs
__device__ u32 g_wfrag[10*15360];

__device__ __forceinline__ float4 ldg4(const float* p){ return __ldg(reinterpret_cast<const float4*>(p)); }
__device__ __forceinline__ void red4(float* p, float a, float b, float c, float d){
    asm volatile("red.global.add.v4.f32 [%0],{%1,%2,%3,%4};"::"l"(p),"f"(a),"f"(b),"f"(c),"f"(d):"memory");
}
__device__ __forceinline__ float wsum(float v){
    #pragma unroll
    for (int o=16;o;o>>=1) v += __shfl_xor_sync(0xffffffffu, v, o);
    return v;
}
__device__ __forceinline__ u32 f2tf32(float v){
    u32 t; asm("cvt.rna.tf32.f32 %0, %1;" : "=r"(t) : "f"(v)); return t;
}
__device__ __forceinline__ void mma_tf32(float* c, u32 a0,u32 a1,u32 a2,u32 a3, u32 b0,u32 b1){
    asm volatile("mma.sync.aligned.m16n8k8.row.col.f32.tf32.tf32.f32 "
        "{%0,%1,%2,%3},{%4,%5,%6,%7},{%8,%9},{%0,%1,%2,%3};"
        : "+f"(c[0]),"+f"(c[1]),"+f"(c[2]),"+f"(c[3])
        : "r"(a0),"r"(a1),"r"(a2),"r"(a3),"r"(b0),"r"(b1));
}

// A-frag (64 rows x 8k per ktile): ((kt*4+mti)*32+lane)*4 + r
__device__ __forceinline__ void st_af(float* base, int row, int k, float v){
    int kt=k>>3, mti=row>>4, rm=row&15, kc=k&7;
    int r = ((rm>>3)&1) + ((kc>>2)<<1);
    int lane = (rm&7)*4 + (kc&3);
    reinterpret_cast<u32*>(base)[((kt*4+mti)*32+lane)*4 + r] = f2tf32(v);
}

// one k-step over warp's 32x32 tile; B fragments from gmem (L2)
__device__ __forceinline__ void mma_step(const float* af, const u32* __restrict__ bw,
                                         int kt, int wm, int lane, float acc[2][4][4]){
    u32 a[2][4], b[4][2];
    #pragma unroll
    for (int nt=0; nt<4; nt++){
        uint2 v = __ldg(reinterpret_cast<const uint2*>(bw + kt*1024 + nt*64));
        b[nt][0]=v.x; b[nt][1]=v.y;
    }
    #pragma unroll
    for (int mt=0; mt<2; mt++){
        float4 v = *reinterpret_cast<const float4*>(af + ((size_t)((kt*4 + wm*2+mt)*32+lane))*4);
        a[mt][0]=__float_as_uint(v.x); a[mt][1]=__float_as_uint(v.y);
        a[mt][2]=__float_as_uint(v.z); a[mt][3]=__float_as_uint(v.w);
    }
    #pragma unroll
    for (int mt=0; mt<2; mt++){
        #pragma unroll
        for (int nt=0; nt<4; nt++)
            mma_tf32(acc[mt][nt], a[mt][0],a[mt][1],a[mt][2],a[mt][3], b[nt][0],b[nt][1]);
    }
}

__device__ __forceinline__ void zero_acc(float acc[2][4][4]){
    #pragma unroll
    for (int i=0;i<2;i++){
        #pragma unroll
        for (int j=0;j<4;j++){
            #pragma unroll
            for (int r=0;r<4;r++) acc[i][j][r]=0.f;
        }
    }
}

// silu(acc + sb[col]) -> A-frag store
__device__ __forceinline__ void epilogue_h(float acc[2][4][4], const float* sb, float* hbase,
                                           int wm, int wn, int lane){
    int r0 = wm*32 + (lane>>2);
    int c0b = wn*32 + 2*(lane&3);
    #pragma unroll
    for (int mt=0; mt<2; mt++){
        int row0 = r0 + mt*16;
        #pragma unroll
        for (int nt=0; nt<4; nt++){
            int col0 = c0b + nt*8;
            #pragma unroll
            for (int ri=0; ri<4; ri++){
                int row = row0 + (ri>>1)*8;
                int col = col0 + (ri&1);
                if (col < 120){
                    float x = acc[mt][nt][ri] + sb[col];
                    st_af(hbase, row, col, x/(1.f+__expf(-x)));
                }
            }
        }
    }
}

// ---------- setup: convert all 10 weights to fragment-layout tf32 ----------
__global__ void conv_weights_kernel(
    const float* __restrict__ w0, const float* __restrict__ w1,
    const float* __restrict__ w2, const float* __restrict__ w3,
    const float* __restrict__ w4, const float* __restrict__ w5,
    const float* __restrict__ w6, const float* __restrict__ w7,
    const float* __restrict__ w8, const float* __restrict__ w9)
{
    int wid = blockIdx.y;
    int l = blockIdx.x*256 + threadIdx.x;
    if (l >= 15360) return;
    const int nktA[10] = {14,3,15,15,15,15,15,15,15,15};
    const int KA[10]   = {112,20,120,120,120,120,120,120,120,120};
    int kt = l>>10;
    if (kt >= nktA[wid]) return;
    const float* W = (wid==0)?w0:(wid==1)?w1:(wid==2)?w2:(wid==3)?w3:(wid==4)?w4:
                     (wid==5)?w5:(wid==6)?w6:(wid==7)?w7:(wid==8)?w8:w9;
    int ld = (wid==9)?112:120;
    int N  = (wid==9)?112:120;
    int K  = KA[wid];
    int rest = l&1023;
    int nti = rest>>6, lane=(rest>>1)&31, r = rest&1;
    int n = nti*8 + (lane>>2);
    int k = kt*8 + (lane&3) + 4*r;
    float v = (n<N && k<K) ? __ldg(W + (size_t)k*ld + n) : 0.f;
    g_wfrag[wid*15360 + l] = f2tf32(v);
}

// ---------- K0: residual init ----------
__global__ void init_out_kernel(const float* __restrict__ xs, const float* __restrict__ xe, float* __restrict__ out){
    size_t i = (size_t)blockIdx.x*blockDim.x + threadIdx.x;
    size_t ns = (size_t)NN*120, ne = (size_t)NN*240;
    if (i < ns) out[i] = xs[i];
    if (i < ne) out[ns + i] = xe[i];
}

// ---------- K1: node LayerNorm + O3 LayerNorm ----------
__global__ void node_norm_kernel(const float* __restrict__ xs_in, const float* __restrict__ xe_in,
                                 const float* __restrict__ lnw, const float* __restrict__ lnb,
                                 const float* __restrict__ o3w){
    int lane = threadIdx.x & 31;
    int node = blockIdx.x*4 + (threadIdx.x >> 5);
    if (node >= NN) return;
    const float* xs = xs_in + (size_t)node*120;
    float v0=xs[lane], v1=xs[lane+32], v2=xs[lane+64], v3=(lane<24)?xs[lane+96]:0.f;
    float s = wsum(v0+v1+v2+v3);
    float q = wsum(v0*v0+v1*v1+v2*v2+v3*v3);
    float mean = s*(1.f/120.f);
    float inv = rsqrtf(q*(1.f/120.f) - mean*mean + 1e-5f);
    float* ns = g_ns + (size_t)node*120;
    ns[lane]    = (v0-mean)*inv*__ldg(lnw+lane)    + __ldg(lnb+lane);
    ns[lane+32] = (v1-mean)*inv*__ldg(lnw+lane+32) + __ldg(lnb+lane+32);
    ns[lane+64] = (v2-mean)*inv*__ldg(lnw+lane+64) + __ldg(lnb+lane+64);
    if (lane<24) ns[lane+96] = (v3-mean)*inv*__ldg(lnw+lane+96) + __ldg(lnb+lane+96);

    const float* xe = xe_in + (size_t)node*240;
    float* ne = g_ne + (size_t)node*240;
    {
        float e0=xe[lane], e1=xe[lane+32];
        float m = wsum(e0+e1)*(1.f/64.f);
        float c0=e0-m, c1=e1-m;
        float r = rsqrtf(wsum(c0*c0+c1*c1)*(1.f/64.f) + 1e-5f);
        ne[lane]    = c0*r*__ldg(o3w+lane);
        ne[lane+32] = c1*r*__ldg(o3w+lane+32);
    }
    {
        float y0=xe[64+lane], y1=xe[96+lane], y2=xe[128+lane];
        float r = rsqrtf(wsum(y0*y0+y1*y1+y2*y2)*(1.f/96.f) + 1e-5f);
        ne[64+lane]  = y0*r*__ldg(o3w+64+(lane)/3);
        ne[96+lane]  = y1*r*__ldg(o3w+64+(32+lane)/3);
        ne[128+lane] = y2*r*__ldg(o3w+64+(64+lane)/3);
    }
    {
        float z0=xe[160+lane], z1=xe[192+lane], z2=(lane<16)?xe[224+lane]:0.f;
        float r = rsqrtf(wsum(z0*z0+z1*z1+z2*z2)*(1.f/80.f) + 1e-5f);
        ne[160+lane] = z0*r*__ldg(o3w+96+(lane)/5);
        ne[192+lane] = z1*r*__ldg(o3w+96+(32+lane)/5);
        if (lane<16) ne[224+lane] = z2*r*__ldg(o3w+96+(64+lane)/5);
    }
}

// ---------- K2: all 6 projections via mma.sync, A staged once ----------
__global__ __launch_bounds__(256,3) void proj_mma_kernel(void){
    __shared__ alignas(16) float af[15*512];
    int tid = threadIdx.x;
    int warp = tid>>5, lane = tid&31;
    int wm = warp>>2, wn = warp&3;
    int row0 = blockIdx.x * 64;

    for (int idx=tid; idx<64*120; idx+=256){
        int row = idx/120, k = idx - row*120;
        st_af(af, row, k, g_ns[(size_t)(row0+row)*120 + k]);
    }
    __syncthreads();

    int boff = (wn*4)*64 + lane*2;
    int r0 = wm*32 + (lane>>2);
    int c0b = wn*32 + 2*(lane&3);

    #pragma unroll
    for (int sel=0; sel<6; sel++){
        const u32* bw = g_wfrag + (4+sel)*15360 + boff;
        float* C = (sel==0)?g_qinv:(sel==1)?g_kinv:(sel==2)?g_vinv:(sel==3)?g_qsph:(sel==4)?g_ksph:g_vsph;
        int ncols = (sel==5)?112:120;
        float acc[2][4][4];
        zero_acc(acc);
        #pragma unroll
        for (int kt=0; kt<15; kt++) mma_step(af, bw, kt, wm, lane, acc);
        #pragma unroll
        for (int mt=0; mt<2; mt++){
            int rowA = r0 + mt*16;
            #pragma unroll
            for (int nt=0; nt<4; nt++){
                int col0 = c0b + nt*8;
                if (col0 < ncols){
                    *reinterpret_cast<float2*>(C + (size_t)(row0+rowA)*ncols   + col0) =
                        make_float2(acc[mt][nt][0], acc[mt][nt][1]);
                    *reinterpret_cast<float2*>(C + (size_t)(row0+rowA+8)*ncols + col0) =
                        make_float2(acc[mt][nt][2], acc[mt][nt][3]);
                }
            }
        }
    }
}

// ---------- fused edge kernel: 64-edge tiles, B fragments from L2 ----------
#define AF1X 0
#define AF2X 7680
#define AFRX 15360
#define XSB1 16896
#define XSB2 17024
#define XSB3 17152
#define XFC  17280
#define EM_FLOATS 17344

__global__ __launch_bounds__(256,3) void edge_mma_kernel(
    const int* __restrict__ ei, const float* __restrict__ rbf, const float* __restrict__ fcut,
    const float* __restrict__ inv_b1, const float* __restrict__ inv_b2,
    const float* __restrict__ rbf_b1, const float* __restrict__ rbf_b2)
{
    extern __shared__ float sm[];
    int tid = threadIdx.x;
    int warp = tid>>5, lane = tid&31;
    int wm = warp>>2, wn = warp&3;
    int e0 = blockIdx.x * 64;

    int boff = (wn*4)*64 + lane*2;
    const u32* bw1  = g_wfrag + 0*15360 + boff;
    const u32* bwr1 = g_wfrag + 1*15360 + boff;
    const u32* bw2  = g_wfrag + 2*15360 + boff;
    const u32* bwr2 = g_wfrag + 3*15360 + boff;

    for (int idx=tid; idx<256; idx+=256){
        int mti = idx>>6, rest = idx&63, ln = rest>>1, r = 2+(rest&1);
        sm[AFRX + ((2*4+mti)*32+ln)*4 + r] = 0.f;
    }
    if (tid < 128){
        sm[XSB1+tid] = (tid<120) ? __ldg(inv_b1+tid) : 0.f;
        sm[XSB2+tid] = (tid<120) ? __ldg(rbf_b1+tid) : 0.f;
        sm[XSB3+tid] = (tid<120) ? (__ldg(inv_b2+tid)+__ldg(rbf_b2+tid)) : 0.f;
    }
    if (tid < 64) sm[XFC+tid] = __ldg(fcut + e0 + tid);

    for (int el = warp; el < 64; el += 8){
        int e = e0 + el;
        int a_n = __ldg(ei+EE+e), b_n = __ldg(ei+e);
        const float* a = g_ne + (size_t)a_n*240;
        const float* b = g_ne + (size_t)b_n*240;
        { float d = __ldg(a+lane)-__ldg(b+lane);       st_af(sm+AF1X, el, lane,    d*d); }
        { float d = __ldg(a+lane+32)-__ldg(b+lane+32); st_af(sm+AF1X, el, lane+32, d*d); }
        { int base = 64 + lane*3; float s=0.f;
          #pragma unroll
          for (int j=0;j<3;j++){ float d=__ldg(a+base+j)-__ldg(b+base+j); s+=d*d; }
          st_af(sm+AF1X, el, 64+lane, s); }
        if (lane<16){ int base = 160 + lane*5; float s=0.f;
          #pragma unroll
          for (int j=0;j<5;j++){ float d=__ldg(a+base+j)-__ldg(b+base+j); s+=d*d; }
          st_af(sm+AF1X, el, 96+lane, s); }
    }
    for (int idx=tid; idx<64*20; idx+=256){
        int row = idx/20, k = idx - row*20;
        st_af(sm+AFRX, row, k, __ldg(rbf + (size_t)(e0+row)*20 + k));
    }
    __syncthreads();

    float acc[2][4][4];
    zero_acc(acc);

    #pragma unroll
    for (int kt=0; kt<3; kt++) mma_step(sm+AFRX, bwr1, kt, wm, lane, acc);
    epilogue_h(acc, sm+XSB2, sm+AF2X, wm, wn, lane);
    zero_acc(acc);

    #pragma unroll
    for (int kt=0; kt<14; kt++) mma_step(sm+AF1X, bw1, kt, wm, lane, acc);
    __syncthreads();
    epilogue_h(acc, sm+XSB1, sm+AF1X, wm, wn, lane);
    zero_acc(acc);
    __syncthreads();

    #pragma unroll
    for (int kt=0; kt<15; kt++) mma_step(sm+AF1X, bw2,  kt, wm, lane, acc);
    #pragma unroll
    for (int kt=0; kt<15; kt++) mma_step(sm+AF2X, bwr2, kt, wm, lane, acc);

    {
        int r0 = wm*32 + (lane>>2);
        int c0b = wn*32 + 2*(lane&3);
        #pragma unroll
        for (int mt=0; mt<2; mt++){
            int rowA = r0 + mt*16;
            float fA = sm[XFC+rowA], fB = sm[XFC+rowA+8];
            #pragma unroll
            for (int nt=0; nt<4; nt++){
                int col0 = c0b + nt*8;
                if (col0 < 120){
                    float2 va, vb;
                    va.x = (acc[mt][nt][0] + sm[XSB3+col0])  *fA;
                    va.y = (acc[mt][nt][1] + sm[XSB3+col0+1])*fA;
                    vb.x = (acc[mt][nt][2] + sm[XSB3+col0])  *fB;
                    vb.y = (acc[mt][nt][3] + sm[XSB3+col0+1])*fB;
                    *reinterpret_cast<float2*>(g_w + (size_t)(e0+rowA)*120   + col0) = va;
                    *reinterpret_cast<float2*>(g_w + (size_t)(e0+rowA+8)*120 + col0) = vb;
                }
            }
        }
    }
}

// ---------- K6: attention + gated messages + scatter ----------
__global__ __launch_bounds__(256) void edge_attn_kernel(const int* __restrict__ ei,
                                                        const float* __restrict__ fcut,
                                                        const float* __restrict__ rsh,
                                                        float* __restrict__ outS,
                                                        float* __restrict__ outE){
    __shared__ float sgate[8][116];
    int warp = threadIdx.x>>5, lane = threadIdx.x&31;
    int e = blockIdx.x*8 + warp;
    int ct = __ldg(ei+e), nb = __ldg(ei+EE+e);
    float fc = __ldg(fcut+e);
    const float* w  = g_w   + (size_t)e*120;
    const float* qi = g_qinv + (size_t)ct*120;
    const float* ki = g_kinv + (size_t)nb*120;
    const float* vi = g_vinv + (size_t)nb*120;
    const float* qs = g_qsph + (size_t)ct*120;
    const float* ks = g_ksph + (size_t)nb*120;
    const float* vs = g_vsph + (size_t)nb*112;

    float s0=0,s1=0,s2=0,s3=0,t0=0,t1=0,t2=0;
    if (lane < 30){
        float4 wv = ldg4(w + 4*lane);
        float4 q  = ldg4(qi + 4*lane), k = ldg4(ki + 4*lane);
        float4 qe = ldg4(qs + 4*lane), ke = ldg4(ks + 4*lane);
        float wa[4]={wv.x,wv.y,wv.z,wv.w};
        float pa[4]={q.x*k.x, q.y*k.y, q.z*k.z, q.w*k.w};
        float pe[4]={qe.x*ke.x, qe.y*ke.y, qe.z*ke.z, qe.w*ke.w};
        #pragma unroll
        for (int j=0;j<4;j++){
            int idx = 4*lane + j;
            float p = wa[j]*pa[j];
            float pq = wa[j]*pe[j];
            int h = idx/30, l = idx/40;
            s0 += (h==0)?p:0.f; s1 += (h==1)?p:0.f; s2 += (h==2)?p:0.f; s3 += (h==3)?p:0.f;
            t0 += (l==0)?pq:0.f; t1 += (l==1)?pq:0.f; t2 += (l==2)?pq:0.f;
        }
    }
    const float SC_S = 0.091287092917527686f;
    const float SC_E = 0.094491118252306805f;
    s0 = wsum(s0)*SC_S; s1 = wsum(s1)*SC_S; s2 = wsum(s2)*SC_S; s3 = wsum(s3)*SC_S;
    t0 = wsum(t0)*SC_E; t1 = wsum(t1)*SC_E; t2 = wsum(t2)*SC_E;

    if (lane < 30){
        float4 v = ldg4(vi + 4*lane);
        float va[4]={v.x,v.y,v.z,v.w}, m[4];
        #pragma unroll
        for (int j=0;j<4;j++){
            int h = (4*lane+j)/30;
            float ss = (h==0)?s0:((h==1)?s1:((h==2)?s2:s3));
            m[j] = ss*va[j];
        }
        red4(outS + (size_t)ct*120 + 4*lane, m[0],m[1],m[2],m[3]);
    }
    if (lane < 28){
        float4 v = ldg4(vs + 4*lane);
        float va[4]={v.x,v.y,v.z,v.w};
        #pragma unroll
        for (int j=0;j<4;j++){
            int ir = 4*lane + j;
            float tl = (ir<64)?t0:((ir<96)?t1:t2);
            sgate[warp][ir] = tl*va[j]*fc;
        }
    }
    __syncwarp();
    if (lane < 30){
        int base = 8*lane;
        float4 r0 = ldg4(rsh + (size_t)e*240 + base);
        float4 r1 = ldg4(rsh + (size_t)e*240 + base + 4);
        float ra[8]={r0.x,r0.y,r0.z,r0.w,r1.x,r1.y,r1.z,r1.w}, m[8];
        #pragma unroll
        for (int j=0;j<8;j++){
            int c = base + j;
            int ir = (c<64)? c : (c<160)? 64+(c-64)/3 : 96+(c-160)/5;
            m[j] = ra[j]*sgate[warp][ir];
        }
        red4(outE + (size_t)ct*240 + base,     m[0],m[1],m[2],m[3]);
        red4(outE + (size_t)ct*240 + base + 4, m[4],m[5],m[6],m[7]);
    }
}

extern "C" void kernel_launch(void* const* d_in, const int* in_sizes, int n_in,
                              void* d_out, int out_size){
    const float* node_scalar=(const float*)d_in[0];
    const float* node_equi  =(const float*)d_in[1];
    const float* rbf        =(const float*)d_in[2];
    const float* fcut       =(const float*)d_in[3];
    const float* rsh        =(const float*)d_in[4];
    const float* ln_w =(const float*)d_in[5];
    const float* ln_b =(const float*)d_in[6];
    const float* o3w  =(const float*)d_in[7];
    const float* Wq   =(const float*)d_in[8];
    const float* Wk   =(const float*)d_in[9];
    const float* Wv   =(const float*)d_in[10];
    const float* Wqs  =(const float*)d_in[11];
    const float* Wks  =(const float*)d_in[12];
    const float* Wvs  =(const float*)d_in[13];
    const float* rbf_w1=(const float*)d_in[14];
    const float* rbf_b1=(const float*)d_in[15];
    const float* rbf_w2=(const float*)d_in[16];
    const float* rbf_b2=(const float*)d_in[17];
    const float* inv_w1=(const float*)d_in[18];
    const float* inv_b1=(const float*)d_in[19];
    const float* inv_w2=(const float*)d_in[20];
    const float* inv_b2=(const float*)d_in[21];
    const int*   ei    =(const int*)d_in[22];

    float* outS = (float*)d_out;
    float* outE = outS + (size_t)NN*120;

    cudaFuncSetAttribute(edge_mma_kernel, cudaFuncAttributeMaxDynamicSharedMemorySize, EM_FLOATS*4);

    conv_weights_kernel<<<dim3(60,10), 256>>>(inv_w1, rbf_w1, inv_w2, rbf_w2,
                                              Wq, Wk, Wv, Wqs, Wks, Wvs);
    init_out_kernel<<<(NN*240 + 255)/256, 256>>>(node_scalar, node_equi, (float*)d_out);
    node_norm_kernel<<<NN/4, 128>>>(node_scalar, node_equi, ln_w, ln_b, o3w);
    proj_mma_kernel<<<NN/64, 256>>>();
    edge_mma_kernel<<<EE/64, 256, EM_FLOATS*4>>>(ei, rbf, fcut, inv_b1, inv_b2, rbf_b1, rbf_b2);
    edge_attn_kernel<<<EE/8, 256>>>(ei, fcut, rsh, outS, outE);
}